// round 14
// baseline (speedup 1.0000x reference)
#include <cuda_runtime.h>
#include <cuda_fp16.h>
#include <cstdint>
#include <cstddef>

// ---------------------------------------------------------------------------
// Problem constants
// ---------------------------------------------------------------------------
#define S_LEN 2048
#define B_SZ  2
#define D_MODEL 512
#define H_HEADS 8
#define DK 64
#define F_FFN 2048
#define M_ROWS (B_SZ * S_LEN)              // 4096
#define OUT_ELEMS (S_LEN * B_SZ * D_MODEL) // 2097152

// Scratch layout (float offsets)
#define OFF_T1   0                         // 2M floats
#define OFF_H    2097152                   // 2M floats
#define OFF_XH   4194304                   // 2M halves = 1M floats
#define OFF_QH   5242880                   // Q,K,VT each 2M halves = 1M floats
#define OFF_KH   6291456
#define OFF_VTH  7340032
#define OFF_GAOH 8388608                   // 1M floats
#define OFF_HH   9437184                   // 1M floats
#define OFF_FFH  10485760                  // 8M halves = 4M floats
#define OFF_WQH  14680064                  // 128K floats each
#define OFF_WKH  14811136
#define OFF_WVH  14942208
#define OFF_WFCH 15073280
#define OFF_W1H  15204352                  // 512K floats
#define OFF_W2H  15728640                  // 512K floats
#define OFF_SH   16252928                  // 67108864 halves = 33554432 floats
#define OFF_PART 49807360                  // 32768*32 float2 = 2097152 floats
#define SCRATCH_FLOATS 51904512

__device__ float g_scratch[SCRATCH_FLOATS];

// ---------------------------------------------------------------------------
// PTX helpers
// ---------------------------------------------------------------------------
__device__ __forceinline__ uint32_t smem_to_u32(const void* p) {
    uint32_t a;
    asm("{ .reg .u64 t; cvta.to.shared.u64 t, %1; cvt.u32.u64 %0, t; }"
        : "=r"(a) : "l"(p));
    return a;
}

#define CP_ASYNC16(dst, src) \
    asm volatile("cp.async.cg.shared.global [%0], [%1], 16;\n" \
                 :: "r"(dst), "l"(src))
#define CP_COMMIT() asm volatile("cp.async.commit_group;\n" ::: "memory")
#define CP_WAIT1()  asm volatile("cp.async.wait_group 1;\n" ::: "memory")
#define CP_WAIT0()  asm volatile("cp.async.wait_group 0;\n" ::: "memory")

__device__ __forceinline__ void mma_f16(float (&dd)[4], const uint32_t (&a)[4],
                                        const uint32_t (&b)[2]) {
    asm volatile(
        "mma.sync.aligned.m16n8k16.row.col.f32.f16.f16.f32 "
        "{%0,%1,%2,%3}, {%4,%5,%6,%7}, {%8,%9}, {%0,%1,%2,%3};\n"
        : "+f"(dd[0]), "+f"(dd[1]), "+f"(dd[2]), "+f"(dd[3])
        : "r"(a[0]), "r"(a[1]), "r"(a[2]), "r"(a[3]), "r"(b[0]), "r"(b[1]));
}

// streaming fp32x4 store (evict-first)
__device__ __forceinline__ void stcs4(float* p, float4 v) {
    asm volatile("st.global.cs.v4.f32 [%0], {%1, %2, %3, %4};\n"
                 :: "l"(p), "f"(v.x), "f"(v.y), "f"(v.z), "f"(v.w) : "memory");
}

// permuted src row: x[m] = src[(s*B + b)] with m = b*S + s
__device__ __forceinline__ int perm_row(int m) {
    return ((m & (S_LEN - 1)) << 1) + (m >> 11);
}

// ---------------------------------------------------------------------------
// Conversion prep: src (permuted) + 6 weight matrices -> fp16
// ---------------------------------------------------------------------------
__global__ void __launch_bounds__(256) convert_all(
    const float* __restrict__ src,
    const float* __restrict__ wq, const float* __restrict__ wk,
    const float* __restrict__ wv, const float* __restrict__ wfc,
    const float* __restrict__ w1, const float* __restrict__ w2,
    __half* __restrict__ xh, __half* __restrict__ wqh, __half* __restrict__ wkh,
    __half* __restrict__ wvh, __half* __restrict__ wfch,
    __half* __restrict__ w1h, __half* __restrict__ w2h) {
    int i4 = blockIdx.x * 256 + threadIdx.x;   // float4 index
    if (i4 < 524288) {                          // xh with row permutation
        int m = i4 >> 7;
        int c = (i4 & 127) << 2;
        float4 v = *(const float4*)(src + (size_t)perm_row(m) * D_MODEL + c);
        __half2* d = (__half2*)(xh + (size_t)m * D_MODEL + c);
        d[0] = __floats2half2_rn(v.x, v.y);
        d[1] = __floats2half2_rn(v.z, v.w);
        return;
    }
    i4 -= 524288;
    const float* sp;
    __half* dp;
    if (i4 < 65536) { sp = wq; dp = wqh; }
    else if (i4 < 131072) { sp = wk; dp = wkh; i4 -= 65536; }
    else if (i4 < 196608) { sp = wv; dp = wvh; i4 -= 131072; }
    else if (i4 < 262144) { sp = wfc; dp = wfch; i4 -= 196608; }
    else if (i4 < 524288) { sp = w1; dp = w1h; i4 -= 262144; }
    else { sp = w2; dp = w2h; i4 -= 524288; }
    float4 v = *(const float4*)(sp + (size_t)i4 * 4);
    __half2* d = (__half2*)(dp + (size_t)i4 * 4);
    d[0] = __floats2half2_rn(v.x, v.y);
    d[1] = __floats2half2_rn(v.z, v.w);
}

// ---------------------------------------------------------------------------
// fp16 mma.sync GEMM: C[m,n] = sum_k A[m,k] * Bw[n,k]  (K-major halves)
// BM=128, BN template, BK=64, 3-stage cp.async ring, 256 threads (4m x 2n),
// 128-byte smem rows with conflict-free 8-chunk XOR swizzle.
// Trailing per-iteration barrier removed (issue happens after the leading
// barrier; 3-stage ring guarantees no same-buffer overlap).
//
// EPI: 0 = fused QKV (z selects B: B0/B1/B2; z<2 plain fp16, z=2 V^T scatter)
//      4 = fp32 out + resid(src perm)
//      5 = fp16 out relu(v + bias)
//      6 = fp32 out + bias + resid(fp32)
// ---------------------------------------------------------------------------
#define STAGES 3

template <int EPI, int BN>
__global__ void __launch_bounds__(256, 2) gemm_h(
    const __half* __restrict__ A, int lda,
    const __half* __restrict__ B0, const __half* __restrict__ B1,
    const __half* __restrict__ B2, int ldb,
    int K, float* __restrict__ C,
    const float* __restrict__ bias, const float* __restrict__ resid,
    int ldc, __half* __restrict__ Chalf) {
    constexpr int NT = BN / 16;
    constexpr int ASTG = 128 * 64;           // halves per A stage
    constexpr int BSTG = BN * 64;
    extern __shared__ __half hsm[];
    __half* smA = hsm;
    __half* smB = hsm + STAGES * ASTG;

    const int tid = threadIdx.x;
    const int w = tid >> 5, lane = tid & 31;
    const int g = lane >> 2, t = lane & 3;
    const int mw = w >> 1, nw = w & 1;
    const int m0 = blockIdx.y * 128, n0 = blockIdx.x * BN;
    const int z = blockIdx.z;

    const __half* Bp = (EPI == 0) ? ((z == 0) ? B0 : (z == 1) ? B1 : B2) : B0;

    const uint32_t sA = smem_to_u32(smA);
    const uint32_t sB = smem_to_u32(smB);

    float d[2][NT][4];
#pragma unroll
    for (int i = 0; i < 2; i++)
#pragma unroll
        for (int j = 0; j < NT; j++)
#pragma unroll
            for (int r = 0; r < 4; r++) d[i][j][r] = 0.f;

    const int NC = K >> 6;

    auto issue = [&](int kc, int stg) {
        int k0 = kc << 6;
#pragma unroll
        for (int i = 0; i < 4; i++) {
            int id = tid + (i << 8);          // 128 rows x 8 chunks
            int r = id >> 3, c = id & 7;
            uint32_t dst = sA + ((stg * ASTG + r * 64 + ((c ^ (r & 7)) << 3)) << 1);
            CP_ASYNC16(dst, A + (size_t)(m0 + r) * lda + k0 + (c << 3));
        }
#pragma unroll
        for (int i = 0; i < BN / 32; i++) {
            int id = tid + (i << 8);
            int r = id >> 3, c = id & 7;
            uint32_t dst = sB + ((stg * BSTG + r * 64 + ((c ^ (r & 7)) << 3)) << 1);
            CP_ASYNC16(dst, Bp + (size_t)(n0 + r) * ldb + k0 + (c << 3));
        }
        CP_COMMIT();
    };

    issue(0, 0);
    if (NC > 1) issue(1, 1);

    for (int kc = 0; kc < NC; kc++) {
        if (kc == NC - 1) { CP_WAIT0(); } else { CP_WAIT1(); }
        __syncthreads();
        if (kc + 2 < NC) issue(kc + 2, (kc + 2) % STAGES);

        int buf = kc % STAGES;
        const __half* Ab = smA + buf * ASTG;
        const __half* Bb = smB + buf * BSTG;
#pragma unroll
        for (int ks = 0; ks < 4; ks++) {
            const int lo = ((2 * ks) ^ g) * 8 + 2 * t;
            const int hi = ((2 * ks + 1) ^ g) * 8 + 2 * t;
            uint32_t a[2][4];
#pragma unroll
            for (int mtw = 0; mtw < 2; mtw++) {
                int r0 = (mw * 2 + mtw) * 16 + g;
                a[mtw][0] = *(const uint32_t*)(Ab + r0 * 64 + lo);
                a[mtw][1] = *(const uint32_t*)(Ab + (r0 + 8) * 64 + lo);
                a[mtw][2] = *(const uint32_t*)(Ab + r0 * 64 + hi);
                a[mtw][3] = *(const uint32_t*)(Ab + (r0 + 8) * 64 + hi);
            }
            uint32_t b[NT][2];
#pragma unroll
            for (int ntw = 0; ntw < NT; ntw++) {
                int nr = (nw * NT + ntw) * 8 + g;
                b[ntw][0] = *(const uint32_t*)(Bb + nr * 64 + lo);
                b[ntw][1] = *(const uint32_t*)(Bb + nr * 64 + hi);
            }
#pragma unroll
            for (int mtw = 0; mtw < 2; mtw++)
#pragma unroll
                for (int ntw = 0; ntw < NT; ntw++)
                    mma_f16(d[mtw][ntw], a[mtw], b[ntw]);
        }
        // trailing barrier removed: next iteration's leading barrier orders
        // these smem reads before any write into this buffer (3-stage ring).
    }

    // ---------------- epilogue ----------------
#pragma unroll
    for (int mtw = 0; mtw < 2; mtw++)
#pragma unroll
        for (int ntw = 0; ntw < NT; ntw++)
#pragma unroll
            for (int half = 0; half < 2; half++) {
                int m = m0 + mw * 32 + mtw * 16 + half * 8 + g;
                int n = n0 + nw * (BN / 2) + ntw * 8 + t * 2;
                float v0 = d[mtw][ntw][half * 2 + 0];
                float v1 = d[mtw][ntw][half * 2 + 1];
                if (EPI == 0) {
                    if (z < 2) {          // Q/K fp16 plain (m, 512)
                        __half* dst = Chalf + (size_t)z * 2097152 +
                                      (size_t)m * D_MODEL + n;
                        *(__half2*)dst = __floats2half2_rn(v0, v1);
                    } else {              // V^T fp16 scatter to (b,h,dk,s)
                        int b = m >> 11, s = m & (S_LEN - 1);
                        int h = n >> 6, dd = n & 63;
                        __half* vt = Chalf + 2 * 2097152;
                        size_t base = ((size_t)((b << 3) + h) * DK + dd) * S_LEN + s;
                        vt[base] = __float2half(v0);
                        vt[base + S_LEN] = __float2half(v1);
                    }
                } else if (EPI == 4) {    // fp32 + resid(src perm)
                    size_t o = (size_t)m * ldc + n;
                    const float* rsrc = resid + (size_t)perm_row(m) * D_MODEL + n;
                    float2 rr = *(const float2*)rsrc;
                    *(float2*)(C + o) = make_float2(v0 + rr.x, v1 + rr.y);
                } else if (EPI == 5) {    // fp16 relu(v + bias)
                    size_t o = (size_t)m * ldc + n;
                    float2 bb = *(const float2*)(bias + n);
                    *(__half2*)(Chalf + o) =
                        __floats2half2_rn(fmaxf(v0 + bb.x, 0.f),
                                          fmaxf(v1 + bb.y, 0.f));
                } else {                  // fp32 + bias + resid
                    size_t o = (size_t)m * ldc + n;
                    float2 bb = *(const float2*)(bias + n);
                    float2 rr = *(const float2*)(resid + o);
                    *(float2*)(C + o) = make_float2(v0 + bb.x + rr.x,
                                                    v1 + bb.y + rr.y);
                }
            }
}

// ---------------------------------------------------------------------------
// Scores (fp16 x fp16): S[bh](m,n) = (Q K^T)(m,n) * 0.125 * sph -> fp16
// + per-(row, 64-col-tile) softmax partials (max, sum-exp) for split softmax.
// BM=BN=128, K=64 (single stage), 256 threads, 128B smem rows.
// sph read via __ldcs (evict-first; read exactly once).
// ---------------------------------------------------------------------------
__global__ void __launch_bounds__(256, 2) scores_f16(
    const __half* __restrict__ qh, const __half* __restrict__ kh,
    const float* __restrict__ sph, __half* __restrict__ s_h,
    float2* __restrict__ part) {
    __shared__ __half sAm[128 * 64];
    __shared__ __half sBm[128 * 64];

    const int tid = threadIdx.x;
    const int w = tid >> 5, lane = tid & 31;
    const int g = lane >> 2, t = lane & 3;
    const int mw = w >> 1, nw = w & 1;
    const int m0 = blockIdx.y * 128, n0 = blockIdx.x * 128;
    const int bh = blockIdx.z;

    size_t hoff = (size_t)(bh >> 3) * (S_LEN * D_MODEL) + (size_t)(bh & 7) * DK;
    const __half* Ap = qh + hoff;
    const __half* Bp = kh + hoff;

    const uint32_t sA = smem_to_u32(sAm);
    const uint32_t sB = smem_to_u32(sBm);

#pragma unroll
    for (int i = 0; i < 4; i++) {
        int id = tid + (i << 8);
        int r = id >> 3, c = id & 7;
        uint32_t dst = sA + ((r * 64 + ((c ^ (r & 7)) << 3)) << 1);
        CP_ASYNC16(dst, Ap + (size_t)(m0 + r) * D_MODEL + (c << 3));
    }
#pragma unroll
    for (int i = 0; i < 4; i++) {
        int id = tid + (i << 8);
        int r = id >> 3, c = id & 7;
        uint32_t dst = sB + ((r * 64 + ((c ^ (r & 7)) << 3)) << 1);
        CP_ASYNC16(dst, Bp + (size_t)(n0 + r) * D_MODEL + (c << 3));
    }
    CP_COMMIT();
    CP_WAIT0();
    __syncthreads();

    float d[2][8][4];
#pragma unroll
    for (int i = 0; i < 2; i++)
#pragma unroll
        for (int j = 0; j < 8; j++)
#pragma unroll
            for (int r = 0; r < 4; r++) d[i][j][r] = 0.f;

#pragma unroll
    for (int ks = 0; ks < 4; ks++) {
        const int lo = ((2 * ks) ^ g) * 8 + 2 * t;
        const int hi = ((2 * ks + 1) ^ g) * 8 + 2 * t;
        uint32_t a[2][4];
#pragma unroll
        for (int mtw = 0; mtw < 2; mtw++) {
            int r0 = (mw * 2 + mtw) * 16 + g;
            a[mtw][0] = *(const uint32_t*)(sAm + r0 * 64 + lo);
            a[mtw][1] = *(const uint32_t*)(sAm + (r0 + 8) * 64 + lo);
            a[mtw][2] = *(const uint32_t*)(sAm + r0 * 64 + hi);
            a[mtw][3] = *(const uint32_t*)(sAm + (r0 + 8) * 64 + hi);
        }
        uint32_t b[8][2];
#pragma unroll
        for (int ntw = 0; ntw < 8; ntw++) {
            int nr = nw * 64 + ntw * 8 + g;
            b[ntw][0] = *(const uint32_t*)(sBm + nr * 64 + lo);
            b[ntw][1] = *(const uint32_t*)(sBm + nr * 64 + hi);
        }
#pragma unroll
        for (int mtw = 0; mtw < 2; mtw++)
#pragma unroll
            for (int ntw = 0; ntw < 8; ntw++)
                mma_f16(d[mtw][ntw], a[mtw], b[ntw]);
    }

    // epilogue: per row (mtw, half) -> store fp16 scores + tile partials
#pragma unroll
    for (int mtw = 0; mtw < 2; mtw++)
#pragma unroll
        for (int half = 0; half < 2; half++) {
            int m = m0 + mw * 32 + mtw * 16 + half * 8 + g;
            float tmp[16];
#pragma unroll
            for (int ntw = 0; ntw < 8; ntw++) {
                int n = n0 + nw * 64 + ntw * 8 + t * 2;
                size_t idx = ((size_t)bh * S_LEN + m) * S_LEN + n;
                float2 sp = __ldcs((const float2*)(sph + idx));
                float v0 = d[mtw][ntw][half * 2 + 0] * 0.125f * sp.x;
                float v1 = d[mtw][ntw][half * 2 + 1] * 0.125f * sp.y;
                __half2 h2 = __floats2half2_rn(v0, v1);
                *(__half2*)(s_h + idx) = h2;
                float2 fr = __half22float2(h2);
                tmp[ntw * 2] = fr.x;
                tmp[ntw * 2 + 1] = fr.y;
            }
            float mx = tmp[0];
#pragma unroll
            for (int i = 1; i < 16; i++) mx = fmaxf(mx, tmp[i]);
            mx = fmaxf(mx, __shfl_xor_sync(0xffffffffu, mx, 1));
            mx = fmaxf(mx, __shfl_xor_sync(0xffffffffu, mx, 2));
            float se = 0.f;
#pragma unroll
            for (int i = 0; i < 16; i++) se += __expf(tmp[i] - mx);
            se += __shfl_xor_sync(0xffffffffu, se, 1);
            se += __shfl_xor_sync(0xffffffffu, se, 2);
            if (t == 0) {
                int tile = blockIdx.x * 2 + nw;   // 32 tiles of 64 cols
                part[((size_t)bh * S_LEN + m) * 32 + tile] =
                    make_float2(mx, se);
            }
        }
}

// ---------------------------------------------------------------------------
// Fused softmax + PV (round-12 structure, 3-stage ring, BK=64 chunks),
// with prefetch moved AFTER the leading barrier so the trailing barrier can
// be dropped: 2 barriers per iteration instead of 3.
// ---------------------------------------------------------------------------
__global__ void __launch_bounds__(256) softmax_pv(
    const __half* __restrict__ s_h, const float2* __restrict__ part,
    const __half* __restrict__ vt, float* __restrict__ p_out,
    __half* __restrict__ gaoh) {
    __shared__ __half smA[3][64 * 64];
    __shared__ __half smB[3][64 * 64];
    __shared__ float rowM[64];
    __shared__ float rowInv[64];

    const int tid = threadIdx.x;
    const int w = tid >> 5, lane = tid & 31;
    const int bh = blockIdx.y;
    const int m0 = blockIdx.x * 64;

    // ---------------- phase 0: global (M, 1/S) per row ----------------
    {
        const float2* pbase = part + ((size_t)bh * S_LEN + m0) * 32;
#pragma unroll
        for (int rr = 0; rr < 8; rr++) {
            int r = w * 8 + rr;
            float2 pm = pbase[(size_t)r * 32 + lane];
            float M = pm.x;
#pragma unroll
            for (int o = 16; o; o >>= 1)
                M = fmaxf(M, __shfl_xor_sync(0xffffffffu, M, o));
            float contrib = pm.y * __expf(pm.x - M);
#pragma unroll
            for (int o = 16; o; o >>= 1)
                contrib += __shfl_xor_sync(0xffffffffu, contrib, o);
            if (lane == 0) {
                rowM[r] = M;
                rowInv[r] = 1.0f / contrib;
            }
        }
    }
    __syncthreads();

    // ---------------- phase 2: normalize + p_out + PV ----------------
    const int g = lane >> 2, t = lane & 3;
    const int mw = w >> 1, nw = w & 1;

    const __half* Ap = s_h + ((size_t)bh * S_LEN + m0) * S_LEN;
    float* Pp = p_out + ((size_t)bh * S_LEN + m0) * S_LEN;
    const __half* Bp = vt + (size_t)bh * DK * S_LEN;
    const uint32_t sA = smem_to_u32(smA);
    const uint32_t sB = smem_to_u32(smB);

    float d[4][4];
#pragma unroll
    for (int j = 0; j < 4; j++)
#pragma unroll
        for (int r = 0; r < 4; r++) d[j][r] = 0.f;

    const int NC = S_LEN / 64;   // 32

    auto issue = [&](int kc, int stg) {
        int k0 = kc << 6;
#pragma unroll
        for (int i = 0; i < 2; i++) {
            int id = tid + (i << 8);
            int r = id >> 3, c = id & 7;
            uint32_t dst = sA + ((stg * 4096 + r * 64 + ((c ^ (r & 7)) << 3)) << 1);
            CP_ASYNC16(dst, Ap + (size_t)r * S_LEN + k0 + (c << 3));
        }
#pragma unroll
        for (int i = 0; i < 2; i++) {
            int id = tid + (i << 8);
            int r = id >> 3, c = id & 7;
            uint32_t dst = sB + ((stg * 4096 + r * 64 + ((c ^ (r & 7)) << 3)) << 1);
            CP_ASYNC16(dst, Bp + (size_t)r * S_LEN + k0 + (c << 3));
        }
        CP_COMMIT();
    };

    issue(0, 0);
    if (NC > 1) issue(1, 1);
    for (int kc = 0; kc < NC; kc++) {
        int k0 = kc << 6;
        if (kc == NC - 1) { CP_WAIT0(); } else { CP_WAIT1(); }
        __syncthreads();
        // prefetch AFTER the barrier: all MMA reads of buffer (kc+2)%3
        // (== (kc-1)%3) are ordered before these writes.
        if (kc + 2 < NC) issue(kc + 2, (kc + 2) % 3);

        int buf = kc % 3;
        __half* Ab = smA[buf];
        const __half* Bb = smB[buf];

        // normalize chunk in place + write fp32 p_attn (streaming)
#pragma unroll
        for (int i = 0; i < 2; i++) {
            int id = tid + (i << 8);
            int r = id >> 3, c = id & 7;
            __half* sp = Ab + r * 64 + ((c ^ (r & 7)) << 3);
            uint4 raw = *(const uint4*)sp;
            const __half2* h2 = (const __half2*)&raw;
            float M = rowM[r], inv = rowInv[r];
            float p[8];
#pragma unroll
            for (int j = 0; j < 4; j++) {
                float2 f = __half22float2(h2[j]);
                p[2 * j] = __expf(f.x - M) * inv;
                p[2 * j + 1] = __expf(f.y - M) * inv;
            }
            float* pd = Pp + (size_t)r * S_LEN + k0 + (c << 3);
            stcs4(pd, make_float4(p[0], p[1], p[2], p[3]));
            stcs4(pd + 4, make_float4(p[4], p[5], p[6], p[7]));
            uint4 pk;
            __half2* pk2 = (__half2*)&pk;
#pragma unroll
            for (int j = 0; j < 4; j++)
                pk2[j] = __floats2half2_rn(p[2 * j], p[2 * j + 1]);
            *(uint4*)sp = pk;
        }
        __syncthreads();

        // PV MMA on normalized tile
#pragma unroll
        for (int ks = 0; ks < 4; ks++) {
            const int lo = ((2 * ks) ^ g) * 8 + 2 * t;
            const int hi = ((2 * ks + 1) ^ g) * 8 + 2 * t;
            uint32_t a[4];
            {
                int r0 = mw * 16 + g;
                a[0] = *(const uint32_t*)(Ab + r0 * 64 + lo);
                a[1] = *(const uint32_t*)(Ab + (r0 + 8) * 64 + lo);
                a[2] = *(const uint32_t*)(Ab + r0 * 64 + hi);
                a[3] = *(const uint32_t*)(Ab + (r0 + 8) * 64 + hi);
            }
            uint32_t b[4][2];
#pragma unroll
            for (int ntw = 0; ntw < 4; ntw++) {
                int nr = nw * 32 + ntw * 8 + g;
                b[ntw][0] = *(const uint32_t*)(Bb + nr * 64 + lo);
                b[ntw][1] = *(const uint32_t*)(Bb + nr * 64 + hi);
            }
#pragma unroll
            for (int ntw = 0; ntw < 4; ntw++)
                mma_f16(d[ntw], a, b[ntw]);
        }
        // trailing barrier removed (see note above).
    }

    int b = bh >> 3, h = bh & 7;
#pragma unroll
    for (int ntw = 0; ntw < 4; ntw++)
#pragma unroll
        for (int half = 0; half < 2; half++) {
            int m = m0 + mw * 16 + half * 8 + g;
            int n = nw * 32 + ntw * 8 + t * 2;
            size_t dst = ((size_t)(b * S_LEN + m)) * D_MODEL + h * DK + n;
            *(__half2*)(gaoh + dst) =
                __floats2half2_rn(d[ntw][half * 2 + 0], d[ntw][half * 2 + 1]);
        }
}

// ---------------------------------------------------------------------------
// LayerNorm kernels
// ---------------------------------------------------------------------------
__device__ __forceinline__ float blockSum256(float v, float* sred) {
#pragma unroll
    for (int o = 16; o; o >>= 1) v += __shfl_xor_sync(0xffffffffu, v, o);
    __syncthreads();
    if ((threadIdx.x & 31) == 0) sred[threadIdx.x >> 5] = v;
    __syncthreads();
    float s = sred[0];
#pragma unroll
    for (int i = 1; i < 8; i++) s += sred[i];
    return s;
}

__global__ void __launch_bounds__(256) ln_double_kernel(
    const float* __restrict__ tin, const float* __restrict__ src,
    const float* __restrict__ ga, const float* __restrict__ ba,
    const float* __restrict__ g1w, const float* __restrict__ b1w,
    float* __restrict__ hout, __half* __restrict__ hh) {
    __shared__ float sred[8];
    int m = blockIdx.x, t = threadIdx.x;
    float2 v = ((const float2*)(tin + (size_t)m * D_MODEL))[t];
    float2 xv = ((const float2*)(src + (size_t)perm_row(m) * D_MODEL))[t];
    float mu = blockSum256(v.x + v.y, sred) * (1.f / 512.f);
    float dx = v.x - mu, dy = v.y - mu;
    float var = blockSum256(dx * dx + dy * dy, sred) * (1.f / 512.f);
    float rs = rsqrtf(var + 1e-6f);
    int d0 = t * 2;
    float u0 = xv.x + dx * rs * ga[d0] + ba[d0];
    float u1 = xv.y + dy * rs * ga[d0 + 1] + ba[d0 + 1];
    mu = blockSum256(u0 + u1, sred) * (1.f / 512.f);
    dx = u0 - mu; dy = u1 - mu;
    var = blockSum256(dx * dx + dy * dy, sred) * (1.f / 512.f);
    rs = rsqrtf(var + 1e-5f);
    float h0 = dx * rs * g1w[d0] + b1w[d0];
    float h1 = dy * rs * g1w[d0 + 1] + b1w[d0 + 1];
    ((float2*)(hout + (size_t)m * D_MODEL))[t] = make_float2(h0, h1);
    ((__half2*)(hh + (size_t)m * D_MODEL))[t] = __floats2half2_rn(h0, h1);
}

__global__ void __launch_bounds__(256) ln_final_kernel(
    const float* __restrict__ tin, const float* __restrict__ g2w,
    const float* __restrict__ b2w, float* __restrict__ out) {
    __shared__ float sred[8];
    int m = blockIdx.x, t = threadIdx.x;
    float2 v = ((const float2*)(tin + (size_t)m * D_MODEL))[t];
    float mu = blockSum256(v.x + v.y, sred) * (1.f / 512.f);
    float dx = v.x - mu, dy = v.y - mu;
    float var = blockSum256(dx * dx + dy * dy, sred) * (1.f / 512.f);
    float rs = rsqrtf(var + 1e-5f);
    int d0 = t * 2;
    int b = m >> 11;
    int s = m & (S_LEN - 1);
    float2 ov = make_float2(dx * rs * g2w[d0] + b2w[d0],
                            dy * rs * g2w[d0 + 1] + b2w[d0 + 1]);
    ((float2*)(out + ((size_t)(s * B_SZ + b)) * D_MODEL))[t] = ov;
}

// ---------------------------------------------------------------------------
// Launch
// ---------------------------------------------------------------------------
#define HSMEM_BN128 (STAGES * (128 + 128) * 64 * 2)   // 98304
#define HSMEM_BN64  (STAGES * (128 + 64) * 64 * 2)    // 73728

extern "C" void kernel_launch(void* const* d_in, const int* in_sizes, int n_in,
                              void* d_out, int out_size) {
    const float* src    = (const float*)d_in[0];
    const float* sph    = (const float*)d_in[1];
    const float* w_qs   = (const float*)d_in[2];
    const float* w_ks   = (const float*)d_in[3];
    const float* w_vs   = (const float*)d_in[4];
    const float* w_fc   = (const float*)d_in[5];
    const float* g_attn = (const float*)d_in[6];
    const float* b_attn = (const float*)d_in[7];
    const float* w1     = (const float*)d_in[8];
    const float* b1     = (const float*)d_in[9];
    const float* w2     = (const float*)d_in[10];
    const float* b2     = (const float*)d_in[11];
    const float* g1w    = (const float*)d_in[12];
    const float* bn1    = (const float*)d_in[13];
    const float* g2w    = (const float*)d_in[14];
    const float* bn2    = (const float*)d_in[15];

    float* out = (float*)d_out;
    float* p_out = out + OUT_ELEMS;

    void* sp = nullptr;
    cudaGetSymbolAddress(&sp, g_scratch);
    float* scr = (float*)sp;
    float* gt1 = scr + OFF_T1;
    float* gh  = scr + OFF_H;
    __half* xh   = (__half*)(scr + OFF_XH);
    __half* qh   = (__half*)(scr + OFF_QH);
    __half* kh   = (__half*)(scr + OFF_KH);
    __half* vt_h = (__half*)(scr + OFF_VTH);
    __half* gaoh = (__half*)(scr + OFF_GAOH);
    __half* hh   = (__half*)(scr + OFF_HH);
    __half* ffh  = (__half*)(scr + OFF_FFH);
    __half* wqh  = (__half*)(scr + OFF_WQH);
    __half* wkh  = (__half*)(scr + OFF_WKH);
    __half* wvh  = (__half*)(scr + OFF_WVH);
    __half* wfch = (__half*)(scr + OFF_WFCH);
    __half* w1h  = (__half*)(scr + OFF_W1H);
    __half* w2h  = (__half*)(scr + OFF_W2H);
    __half* s_h  = (__half*)(scr + OFF_SH);
    float2* part = (float2*)(scr + OFF_PART);

    cudaFuncSetAttribute(gemm_h<0, 128>,
                         cudaFuncAttributeMaxDynamicSharedMemorySize, HSMEM_BN128);
    cudaFuncSetAttribute(gemm_h<4, 64>,
                         cudaFuncAttributeMaxDynamicSharedMemorySize, HSMEM_BN64);
    cudaFuncSetAttribute(gemm_h<5, 128>,
                         cudaFuncAttributeMaxDynamicSharedMemorySize, HSMEM_BN128);
    cudaFuncSetAttribute(gemm_h<6, 64>,
                         cudaFuncAttributeMaxDynamicSharedMemorySize, HSMEM_BN64);

    // 0. fp16 conversions (src perm + all weights)
    convert_all<<<5120, 256>>>(src, w_qs, w_ks, w_vs, w_fc, w1, w2,
                               xh, wqh, wkh, wvh, wfch, w1h, w2h);

    // 1. fused QKV (fp16): z=0 Q, z=1 K, z=2 V^T
    dim3 gqkv(D_MODEL / 128, M_ROWS / 128, 3);
    gemm_h<0, 128><<<gqkv, 256, HSMEM_BN128>>>(
        xh, D_MODEL, wqh, wkh, wvh, D_MODEL, D_MODEL,
        nullptr, nullptr, nullptr, 0, qh);

    // 2. scores = (Q K^T) * 0.125 * sph -> fp16 + softmax partials
    dim3 gsc(S_LEN / 128, S_LEN / 128, B_SZ * H_HEADS);
    scores_f16<<<gsc, 256>>>(qh, kh, sph, s_h, part);

    // 3. fused softmax + PV -> p_out fp32 (streaming) + gaoh fp16
    softmax_pv<<<dim3(S_LEN / 64, B_SZ * H_HEADS), 256>>>(s_h, part, vt_h,
                                                          p_out, gaoh);

    // 4. fc projection + residual(src perm) -> gt1 fp32
    dim3 gfc(D_MODEL / 64, M_ROWS / 128, 1);
    gemm_h<4, 64><<<gfc, 256, HSMEM_BN64>>>(
        gaoh, D_MODEL, wfch, nullptr, nullptr, D_MODEL, D_MODEL,
        gt1, nullptr, src, D_MODEL, nullptr);

    // 5. double LayerNorm -> h fp32 + hh fp16
    ln_double_kernel<<<M_ROWS, 256>>>(gt1, src, g_attn, b_attn, g1w, bn1,
                                      gh, hh);

    // 6. FFN up: relu(h @ w1^T + b1) -> ffh fp16
    dim3 gffn(F_FFN / 128, M_ROWS / 128, 1);
    gemm_h<5, 128><<<gffn, 256, HSMEM_BN128>>>(
        hh, D_MODEL, w1h, nullptr, nullptr, D_MODEL, D_MODEL,
        nullptr, b1, nullptr, F_FFN, ffh);

    // 7. FFN down + b2 + residual(h) -> gt1 fp32
    gemm_h<6, 64><<<gfc, 256, HSMEM_BN64>>>(
        ffh, F_FFN, w2h, nullptr, nullptr, F_FFN, F_FFN,
        gt1, b2, gh, D_MODEL, nullptr);

    // 8. final LN + transposed store
    ln_final_kernel<<<M_ROWS, 256>>>(gt1, g2w, bn2, out);
}

// round 15
// speedup vs baseline: 1.3736x; 1.3736x over previous
#include <cuda_runtime.h>
#include <cuda_fp16.h>
#include <cstdint>
#include <cstddef>

// ---------------------------------------------------------------------------
// Problem constants
// ---------------------------------------------------------------------------
#define S_LEN 2048
#define B_SZ  2
#define D_MODEL 512
#define H_HEADS 8
#define DK 64
#define F_FFN 2048
#define M_ROWS (B_SZ * S_LEN)              // 4096
#define OUT_ELEMS (S_LEN * B_SZ * D_MODEL) // 2097152

// Scratch layout (float offsets)
#define OFF_T1   0                         // 2M floats
#define OFF_H    2097152                   // 2M floats
#define OFF_XH   4194304                   // 2M halves = 1M floats
#define OFF_QH   5242880                   // Q,K,VT each 2M halves = 1M floats
#define OFF_KH   6291456
#define OFF_VTH  7340032
#define OFF_GAOH 8388608                   // 1M floats
#define OFF_HH   9437184                   // 1M floats
#define OFF_FFH  10485760                  // 8M halves = 4M floats
#define OFF_WQH  14680064                  // 128K floats each
#define OFF_WKH  14811136
#define OFF_WVH  14942208
#define OFF_WFCH 15073280
#define OFF_W1H  15204352                  // 512K floats
#define OFF_W2H  15728640                  // 512K floats
#define OFF_SH   16252928                  // 67108864 halves = 33554432 floats
#define OFF_PART 49807360                  // 32768*32 float2 = 2097152 floats
#define SCRATCH_FLOATS 51904512

__device__ float g_scratch[SCRATCH_FLOATS];

// ---------------------------------------------------------------------------
// PTX helpers
// ---------------------------------------------------------------------------
__device__ __forceinline__ uint32_t smem_to_u32(const void* p) {
    uint32_t a;
    asm("{ .reg .u64 t; cvta.to.shared.u64 t, %1; cvt.u32.u64 %0, t; }"
        : "=r"(a) : "l"(p));
    return a;
}

#define CP_ASYNC16(dst, src) \
    asm volatile("cp.async.cg.shared.global [%0], [%1], 16;\n" \
                 :: "r"(dst), "l"(src))
#define CP_COMMIT() asm volatile("cp.async.commit_group;\n" ::: "memory")
#define CP_WAIT2()  asm volatile("cp.async.wait_group 2;\n" ::: "memory")
#define CP_WAIT1()  asm volatile("cp.async.wait_group 1;\n" ::: "memory")
#define CP_WAIT0()  asm volatile("cp.async.wait_group 0;\n" ::: "memory")

__device__ __forceinline__ void mma_f16(float (&dd)[4], const uint32_t (&a)[4],
                                        const uint32_t (&b)[2]) {
    asm volatile(
        "mma.sync.aligned.m16n8k16.row.col.f32.f16.f16.f32 "
        "{%0,%1,%2,%3}, {%4,%5,%6,%7}, {%8,%9}, {%0,%1,%2,%3};\n"
        : "+f"(dd[0]), "+f"(dd[1]), "+f"(dd[2]), "+f"(dd[3])
        : "r"(a[0]), "r"(a[1]), "r"(a[2]), "r"(a[3]), "r"(b[0]), "r"(b[1]));
}

// streaming fp32x4 store (evict-first)
__device__ __forceinline__ void stcs4(float* p, float4 v) {
    asm volatile("st.global.cs.v4.f32 [%0], {%1, %2, %3, %4};\n"
                 :: "l"(p), "f"(v.x), "f"(v.y), "f"(v.z), "f"(v.w) : "memory");
}

// permuted src row: x[m] = src[(s*B + b)] with m = b*S + s
__device__ __forceinline__ int perm_row(int m) {
    return ((m & (S_LEN - 1)) << 1) + (m >> 11);
}

// ---------------------------------------------------------------------------
// Conversion prep: src (permuted) + 6 weight matrices -> fp16
// ---------------------------------------------------------------------------
__global__ void __launch_bounds__(256) convert_all(
    const float* __restrict__ src,
    const float* __restrict__ wq, const float* __restrict__ wk,
    const float* __restrict__ wv, const float* __restrict__ wfc,
    const float* __restrict__ w1, const float* __restrict__ w2,
    __half* __restrict__ xh, __half* __restrict__ wqh, __half* __restrict__ wkh,
    __half* __restrict__ wvh, __half* __restrict__ wfch,
    __half* __restrict__ w1h, __half* __restrict__ w2h) {
    int i4 = blockIdx.x * 256 + threadIdx.x;   // float4 index
    if (i4 < 524288) {                          // xh with row permutation
        int m = i4 >> 7;
        int c = (i4 & 127) << 2;
        float4 v = *(const float4*)(src + (size_t)perm_row(m) * D_MODEL + c);
        __half2* d = (__half2*)(xh + (size_t)m * D_MODEL + c);
        d[0] = __floats2half2_rn(v.x, v.y);
        d[1] = __floats2half2_rn(v.z, v.w);
        return;
    }
    i4 -= 524288;
    const float* sp;
    __half* dp;
    if (i4 < 65536) { sp = wq; dp = wqh; }
    else if (i4 < 131072) { sp = wk; dp = wkh; i4 -= 65536; }
    else if (i4 < 196608) { sp = wv; dp = wvh; i4 -= 131072; }
    else if (i4 < 262144) { sp = wfc; dp = wfch; i4 -= 196608; }
    else if (i4 < 524288) { sp = w1; dp = w1h; i4 -= 262144; }
    else { sp = w2; dp = w2h; i4 -= 524288; }
    float4 v = *(const float4*)(sp + (size_t)i4 * 4);
    __half2* d = (__half2*)(dp + (size_t)i4 * 4);
    d[0] = __floats2half2_rn(v.x, v.y);
    d[1] = __floats2half2_rn(v.z, v.w);
}

// ---------------------------------------------------------------------------
// fp16 mma.sync GEMM: C[m,n] = sum_k A[m,k] * Bw[n,k]  (K-major halves)
// BM=128, BN template, BK=64, 3-stage cp.async ring, 256 threads (4m x 2n),
// 128-byte smem rows with conflict-free 8-chunk XOR swizzle.
//
// EPI: 0 = fused QKV (z selects B: B0/B1/B2; z<2 plain fp16, z=2 V^T scatter)
//      4 = fp32 out + resid(src perm)
//      5 = fp16 out relu(v + bias)
//      6 = fp32 out + bias + resid(fp32)
// ---------------------------------------------------------------------------
#define STAGES 3

template <int EPI, int BN>
__global__ void __launch_bounds__(256, 2) gemm_h(
    const __half* __restrict__ A, int lda,
    const __half* __restrict__ B0, const __half* __restrict__ B1,
    const __half* __restrict__ B2, int ldb,
    int K, float* __restrict__ C,
    const float* __restrict__ bias, const float* __restrict__ resid,
    int ldc, __half* __restrict__ Chalf) {
    constexpr int NT = BN / 16;
    constexpr int ASTG = 128 * 64;           // halves per A stage
    constexpr int BSTG = BN * 64;
    extern __shared__ __half hsm[];
    __half* smA = hsm;
    __half* smB = hsm + STAGES * ASTG;

    const int tid = threadIdx.x;
    const int w = tid >> 5, lane = tid & 31;
    const int g = lane >> 2, t = lane & 3;
    const int mw = w >> 1, nw = w & 1;
    const int m0 = blockIdx.y * 128, n0 = blockIdx.x * BN;
    const int z = blockIdx.z;

    const __half* Bp = (EPI == 0) ? ((z == 0) ? B0 : (z == 1) ? B1 : B2) : B0;

    const uint32_t sA = smem_to_u32(smA);
    const uint32_t sB = smem_to_u32(smB);

    float d[2][NT][4];
#pragma unroll
    for (int i = 0; i < 2; i++)
#pragma unroll
        for (int j = 0; j < NT; j++)
#pragma unroll
            for (int r = 0; r < 4; r++) d[i][j][r] = 0.f;

    const int NC = K >> 6;

    auto issue = [&](int kc, int stg) {
        int k0 = kc << 6;
#pragma unroll
        for (int i = 0; i < 4; i++) {
            int id = tid + (i << 8);          // 128 rows x 8 chunks
            int r = id >> 3, c = id & 7;
            uint32_t dst = sA + ((stg * ASTG + r * 64 + ((c ^ (r & 7)) << 3)) << 1);
            CP_ASYNC16(dst, A + (size_t)(m0 + r) * lda + k0 + (c << 3));
        }
#pragma unroll
        for (int i = 0; i < BN / 32; i++) {
            int id = tid + (i << 8);
            int r = id >> 3, c = id & 7;
            uint32_t dst = sB + ((stg * BSTG + r * 64 + ((c ^ (r & 7)) << 3)) << 1);
            CP_ASYNC16(dst, Bp + (size_t)(n0 + r) * ldb + k0 + (c << 3));
        }
        CP_COMMIT();
    };

    issue(0, 0);
    if (NC > 1) issue(1, 1);

    for (int kc = 0; kc < NC; kc++) {
        if (kc == NC - 1) { CP_WAIT0(); } else { CP_WAIT1(); }
        __syncthreads();
        if (kc + 2 < NC) issue(kc + 2, (kc + 2) % STAGES);

        int buf = kc % STAGES;
        const __half* Ab = smA + buf * ASTG;
        const __half* Bb = smB + buf * BSTG;
#pragma unroll
        for (int ks = 0; ks < 4; ks++) {
            const int lo = ((2 * ks) ^ g) * 8 + 2 * t;
            const int hi = ((2 * ks + 1) ^ g) * 8 + 2 * t;
            uint32_t a[2][4];
#pragma unroll
            for (int mtw = 0; mtw < 2; mtw++) {
                int r0 = (mw * 2 + mtw) * 16 + g;
                a[mtw][0] = *(const uint32_t*)(Ab + r0 * 64 + lo);
                a[mtw][1] = *(const uint32_t*)(Ab + (r0 + 8) * 64 + lo);
                a[mtw][2] = *(const uint32_t*)(Ab + r0 * 64 + hi);
                a[mtw][3] = *(const uint32_t*)(Ab + (r0 + 8) * 64 + hi);
            }
            uint32_t b[NT][2];
#pragma unroll
            for (int ntw = 0; ntw < NT; ntw++) {
                int nr = (nw * NT + ntw) * 8 + g;
                b[ntw][0] = *(const uint32_t*)(Bb + nr * 64 + lo);
                b[ntw][1] = *(const uint32_t*)(Bb + nr * 64 + hi);
            }
#pragma unroll
            for (int mtw = 0; mtw < 2; mtw++)
#pragma unroll
                for (int ntw = 0; ntw < NT; ntw++)
                    mma_f16(d[mtw][ntw], a[mtw], b[ntw]);
        }
        __syncthreads();
    }

    // ---------------- epilogue ----------------
#pragma unroll
    for (int mtw = 0; mtw < 2; mtw++)
#pragma unroll
        for (int ntw = 0; ntw < NT; ntw++)
#pragma unroll
            for (int half = 0; half < 2; half++) {
                int m = m0 + mw * 32 + mtw * 16 + half * 8 + g;
                int n = n0 + nw * (BN / 2) + ntw * 8 + t * 2;
                float v0 = d[mtw][ntw][half * 2 + 0];
                float v1 = d[mtw][ntw][half * 2 + 1];
                if (EPI == 0) {
                    if (z < 2) {          // Q/K fp16 plain (m, 512)
                        __half* dst = Chalf + (size_t)z * 2097152 +
                                      (size_t)m * D_MODEL + n;
                        *(__half2*)dst = __floats2half2_rn(v0, v1);
                    } else {              // V^T fp16 scatter to (b,h,dk,s)
                        int b = m >> 11, s = m & (S_LEN - 1);
                        int h = n >> 6, dd = n & 63;
                        __half* vt = Chalf + 2 * 2097152;
                        size_t base = ((size_t)((b << 3) + h) * DK + dd) * S_LEN + s;
                        vt[base] = __float2half(v0);
                        vt[base + S_LEN] = __float2half(v1);
                    }
                } else if (EPI == 4) {    // fp32 + resid(src perm)
                    size_t o = (size_t)m * ldc + n;
                    const float* rsrc = resid + (size_t)perm_row(m) * D_MODEL + n;
                    float2 rr = *(const float2*)rsrc;
                    *(float2*)(C + o) = make_float2(v0 + rr.x, v1 + rr.y);
                } else if (EPI == 5) {    // fp16 relu(v + bias)
                    size_t o = (size_t)m * ldc + n;
                    float2 bb = *(const float2*)(bias + n);
                    *(__half2*)(Chalf + o) =
                        __floats2half2_rn(fmaxf(v0 + bb.x, 0.f),
                                          fmaxf(v1 + bb.y, 0.f));
                } else {                  // fp32 + bias + resid
                    size_t o = (size_t)m * ldc + n;
                    float2 bb = *(const float2*)(bias + n);
                    float2 rr = *(const float2*)(resid + o);
                    *(float2*)(C + o) = make_float2(v0 + bb.x + rr.x,
                                                    v1 + bb.y + rr.y);
                }
            }
}

// ---------------------------------------------------------------------------
// Scores (fp16 x fp16): S[bh](m,n) = (Q K^T)(m,n) * 0.125 * sph -> fp16
// + per-(row, 64-col-tile) softmax partials (max, sum-exp) for split softmax.
// BM=BN=128, K=64 (single stage), 256 threads, 128B smem rows.
// sph read via __ldcs (evict-first; read exactly once).
// ---------------------------------------------------------------------------
__global__ void __launch_bounds__(256, 2) scores_f16(
    const __half* __restrict__ qh, const __half* __restrict__ kh,
    const float* __restrict__ sph, __half* __restrict__ s_h,
    float2* __restrict__ part) {
    __shared__ __half sAm[128 * 64];
    __shared__ __half sBm[128 * 64];

    const int tid = threadIdx.x;
    const int w = tid >> 5, lane = tid & 31;
    const int g = lane >> 2, t = lane & 3;
    const int mw = w >> 1, nw = w & 1;
    const int m0 = blockIdx.y * 128, n0 = blockIdx.x * 128;
    const int bh = blockIdx.z;

    size_t hoff = (size_t)(bh >> 3) * (S_LEN * D_MODEL) + (size_t)(bh & 7) * DK;
    const __half* Ap = qh + hoff;
    const __half* Bp = kh + hoff;

    const uint32_t sA = smem_to_u32(sAm);
    const uint32_t sB = smem_to_u32(sBm);

#pragma unroll
    for (int i = 0; i < 4; i++) {
        int id = tid + (i << 8);
        int r = id >> 3, c = id & 7;
        uint32_t dst = sA + ((r * 64 + ((c ^ (r & 7)) << 3)) << 1);
        CP_ASYNC16(dst, Ap + (size_t)(m0 + r) * D_MODEL + (c << 3));
    }
#pragma unroll
    for (int i = 0; i < 4; i++) {
        int id = tid + (i << 8);
        int r = id >> 3, c = id & 7;
        uint32_t dst = sB + ((r * 64 + ((c ^ (r & 7)) << 3)) << 1);
        CP_ASYNC16(dst, Bp + (size_t)(n0 + r) * D_MODEL + (c << 3));
    }
    CP_COMMIT();
    CP_WAIT0();
    __syncthreads();

    float d[2][8][4];
#pragma unroll
    for (int i = 0; i < 2; i++)
#pragma unroll
        for (int j = 0; j < 8; j++)
#pragma unroll
            for (int r = 0; r < 4; r++) d[i][j][r] = 0.f;

#pragma unroll
    for (int ks = 0; ks < 4; ks++) {
        const int lo = ((2 * ks) ^ g) * 8 + 2 * t;
        const int hi = ((2 * ks + 1) ^ g) * 8 + 2 * t;
        uint32_t a[2][4];
#pragma unroll
        for (int mtw = 0; mtw < 2; mtw++) {
            int r0 = (mw * 2 + mtw) * 16 + g;
            a[mtw][0] = *(const uint32_t*)(sAm + r0 * 64 + lo);
            a[mtw][1] = *(const uint32_t*)(sAm + (r0 + 8) * 64 + lo);
            a[mtw][2] = *(const uint32_t*)(sAm + r0 * 64 + hi);
            a[mtw][3] = *(const uint32_t*)(sAm + (r0 + 8) * 64 + hi);
        }
        uint32_t b[8][2];
#pragma unroll
        for (int ntw = 0; ntw < 8; ntw++) {
            int nr = nw * 64 + ntw * 8 + g;
            b[ntw][0] = *(const uint32_t*)(sBm + nr * 64 + lo);
            b[ntw][1] = *(const uint32_t*)(sBm + nr * 64 + hi);
        }
#pragma unroll
        for (int mtw = 0; mtw < 2; mtw++)
#pragma unroll
            for (int ntw = 0; ntw < 8; ntw++)
                mma_f16(d[mtw][ntw], a[mtw], b[ntw]);
    }

    // epilogue: per row (mtw, half) -> store fp16 scores + tile partials
#pragma unroll
    for (int mtw = 0; mtw < 2; mtw++)
#pragma unroll
        for (int half = 0; half < 2; half++) {
            int m = m0 + mw * 32 + mtw * 16 + half * 8 + g;
            float tmp[16];
#pragma unroll
            for (int ntw = 0; ntw < 8; ntw++) {
                int n = n0 + nw * 64 + ntw * 8 + t * 2;
                size_t idx = ((size_t)bh * S_LEN + m) * S_LEN + n;
                float2 sp = __ldcs((const float2*)(sph + idx));
                float v0 = d[mtw][ntw][half * 2 + 0] * 0.125f * sp.x;
                float v1 = d[mtw][ntw][half * 2 + 1] * 0.125f * sp.y;
                __half2 h2 = __floats2half2_rn(v0, v1);
                *(__half2*)(s_h + idx) = h2;
                float2 fr = __half22float2(h2);
                tmp[ntw * 2] = fr.x;
                tmp[ntw * 2 + 1] = fr.y;
            }
            float mx = tmp[0];
#pragma unroll
            for (int i = 1; i < 16; i++) mx = fmaxf(mx, tmp[i]);
            mx = fmaxf(mx, __shfl_xor_sync(0xffffffffu, mx, 1));
            mx = fmaxf(mx, __shfl_xor_sync(0xffffffffu, mx, 2));
            float se = 0.f;
#pragma unroll
            for (int i = 0; i < 16; i++) se += __expf(tmp[i] - mx);
            se += __shfl_xor_sync(0xffffffffu, se, 1);
            se += __shfl_xor_sync(0xffffffffu, se, 2);
            if (t == 0) {
                int tile = blockIdx.x * 2 + nw;   // 32 tiles of 64 cols
                part[((size_t)bh * S_LEN + m) * 32 + tile] =
                    make_float2(mx, se);
            }
        }
}

// ---------------------------------------------------------------------------
// Fused softmax + PV without the p_h round-trip (round-12 structure).
// One CTA: 64 q-rows of one (b,h). 3-stage cp.async ring; p_out via
// streaming stores (st.global.cs).
// ---------------------------------------------------------------------------
__global__ void __launch_bounds__(256) softmax_pv(
    const __half* __restrict__ s_h, const float2* __restrict__ part,
    const __half* __restrict__ vt, float* __restrict__ p_out,
    __half* __restrict__ gaoh) {
    __shared__ __half smA[3][64 * 64];
    __shared__ __half smB[3][64 * 64];
    __shared__ float rowM[64];
    __shared__ float rowInv[64];

    const int tid = threadIdx.x;
    const int w = tid >> 5, lane = tid & 31;
    const int bh = blockIdx.y;
    const int m0 = blockIdx.x * 64;

    // ---------------- phase 0: global (M, 1/S) per row ----------------
    {
        const float2* pbase = part + ((size_t)bh * S_LEN + m0) * 32;
#pragma unroll
        for (int rr = 0; rr < 8; rr++) {
            int r = w * 8 + rr;
            float2 pm = pbase[(size_t)r * 32 + lane];   // lane = tile 0..31
            float M = pm.x;
#pragma unroll
            for (int o = 16; o; o >>= 1)
                M = fmaxf(M, __shfl_xor_sync(0xffffffffu, M, o));
            float contrib = pm.y * __expf(pm.x - M);
#pragma unroll
            for (int o = 16; o; o >>= 1)
                contrib += __shfl_xor_sync(0xffffffffu, contrib, o);
            if (lane == 0) {
                rowM[r] = M;
                rowInv[r] = 1.0f / contrib;
            }
        }
    }
    __syncthreads();

    // ---------------- phase 2: normalize + p_out + PV ----------------
    const int g = lane >> 2, t = lane & 3;
    const int mw = w >> 1, nw = w & 1;

    const __half* Ap = s_h + ((size_t)bh * S_LEN + m0) * S_LEN;
    float* Pp = p_out + ((size_t)bh * S_LEN + m0) * S_LEN;
    const __half* Bp = vt + (size_t)bh * DK * S_LEN;
    const uint32_t sA = smem_to_u32(smA);
    const uint32_t sB = smem_to_u32(smB);

    float d[4][4];
#pragma unroll
    for (int j = 0; j < 4; j++)
#pragma unroll
        for (int r = 0; r < 4; r++) d[j][r] = 0.f;

    const int NC = S_LEN / 64;   // 32

    auto issue = [&](int kc, int stg) {
        int k0 = kc << 6;
#pragma unroll
        for (int i = 0; i < 2; i++) {
            int id = tid + (i << 8);
            int r = id >> 3, c = id & 7;
            uint32_t dst = sA + ((stg * 4096 + r * 64 + ((c ^ (r & 7)) << 3)) << 1);
            CP_ASYNC16(dst, Ap + (size_t)r * S_LEN + k0 + (c << 3));
        }
#pragma unroll
        for (int i = 0; i < 2; i++) {
            int id = tid + (i << 8);
            int r = id >> 3, c = id & 7;
            uint32_t dst = sB + ((stg * 4096 + r * 64 + ((c ^ (r & 7)) << 3)) << 1);
            CP_ASYNC16(dst, Bp + (size_t)r * S_LEN + k0 + (c << 3));
        }
        CP_COMMIT();
    };

    issue(0, 0);
    if (NC > 1) issue(1, 1);
    for (int kc = 0; kc < NC; kc++) {
        int k0 = kc << 6;
        if (kc + 2 < NC) {
            issue(kc + 2, (kc + 2) % 3);
            CP_WAIT2();
        } else if (kc + 1 < NC) {
            CP_WAIT1();
        } else {
            CP_WAIT0();
        }
        __syncthreads();
        int buf = kc % 3;
        __half* Ab = smA[buf];
        const __half* Bb = smB[buf];

        // normalize chunk in place + write fp32 p_attn (streaming)
#pragma unroll
        for (int i = 0; i < 2; i++) {
            int id = tid + (i << 8);
            int r = id >> 3, c = id & 7;
            __half* sp = Ab + r * 64 + ((c ^ (r & 7)) << 3);
            uint4 raw = *(const uint4*)sp;
            const __half2* h2 = (const __half2*)&raw;
            float M = rowM[r], inv = rowInv[r];
            float p[8];
#pragma unroll
            for (int j = 0; j < 4; j++) {
                float2 f = __half22float2(h2[j]);
                p[2 * j] = __expf(f.x - M) * inv;
                p[2 * j + 1] = __expf(f.y - M) * inv;
            }
            float* pd = Pp + (size_t)r * S_LEN + k0 + (c << 3);
            stcs4(pd, make_float4(p[0], p[1], p[2], p[3]));
            stcs4(pd + 4, make_float4(p[4], p[5], p[6], p[7]));
            uint4 pk;
            __half2* pk2 = (__half2*)&pk;
#pragma unroll
            for (int j = 0; j < 4; j++)
                pk2[j] = __floats2half2_rn(p[2 * j], p[2 * j + 1]);
            *(uint4*)sp = pk;
        }
        __syncthreads();

        // PV MMA on normalized tile
#pragma unroll
        for (int ks = 0; ks < 4; ks++) {
            const int lo = ((2 * ks) ^ g) * 8 + 2 * t;
            const int hi = ((2 * ks + 1) ^ g) * 8 + 2 * t;
            uint32_t a[4];
            {
                int r0 = mw * 16 + g;
                a[0] = *(const uint32_t*)(Ab + r0 * 64 + lo);
                a[1] = *(const uint32_t*)(Ab + (r0 + 8) * 64 + lo);
                a[2] = *(const uint32_t*)(Ab + r0 * 64 + hi);
                a[3] = *(const uint32_t*)(Ab + (r0 + 8) * 64 + hi);
            }
            uint32_t b[4][2];
#pragma unroll
            for (int ntw = 0; ntw < 4; ntw++) {
                int nr = nw * 32 + ntw * 8 + g;
                b[ntw][0] = *(const uint32_t*)(Bb + nr * 64 + lo);
                b[ntw][1] = *(const uint32_t*)(Bb + nr * 64 + hi);
            }
#pragma unroll
            for (int ntw = 0; ntw < 4; ntw++)
                mma_f16(d[ntw], a, b[ntw]);
        }
        __syncthreads();
    }

    int b = bh >> 3, h = bh & 7;
#pragma unroll
    for (int ntw = 0; ntw < 4; ntw++)
#pragma unroll
        for (int half = 0; half < 2; half++) {
            int m = m0 + mw * 16 + half * 8 + g;
            int n = nw * 32 + ntw * 8 + t * 2;
            size_t dst = ((size_t)(b * S_LEN + m)) * D_MODEL + h * DK + n;
            *(__half2*)(gaoh + dst) =
                __floats2half2_rn(d[ntw][half * 2 + 0], d[ntw][half * 2 + 1]);
        }
}

// ---------------------------------------------------------------------------
// LayerNorm kernels
// ---------------------------------------------------------------------------
__device__ __forceinline__ float blockSum256(float v, float* sred) {
#pragma unroll
    for (int o = 16; o; o >>= 1) v += __shfl_xor_sync(0xffffffffu, v, o);
    __syncthreads();
    if ((threadIdx.x & 31) == 0) sred[threadIdx.x >> 5] = v;
    __syncthreads();
    float s = sred[0];
#pragma unroll
    for (int i = 1; i < 8; i++) s += sred[i];
    return s;
}

__global__ void __launch_bounds__(256) ln_double_kernel(
    const float* __restrict__ tin, const float* __restrict__ src,
    const float* __restrict__ ga, const float* __restrict__ ba,
    const float* __restrict__ g1w, const float* __restrict__ b1w,
    float* __restrict__ hout, __half* __restrict__ hh) {
    __shared__ float sred[8];
    int m = blockIdx.x, t = threadIdx.x;
    float2 v = ((const float2*)(tin + (size_t)m * D_MODEL))[t];
    float2 xv = ((const float2*)(src + (size_t)perm_row(m) * D_MODEL))[t];
    float mu = blockSum256(v.x + v.y, sred) * (1.f / 512.f);
    float dx = v.x - mu, dy = v.y - mu;
    float var = blockSum256(dx * dx + dy * dy, sred) * (1.f / 512.f);
    float rs = rsqrtf(var + 1e-6f);
    int d0 = t * 2;
    float u0 = xv.x + dx * rs * ga[d0] + ba[d0];
    float u1 = xv.y + dy * rs * ga[d0 + 1] + ba[d0 + 1];
    mu = blockSum256(u0 + u1, sred) * (1.f / 512.f);
    dx = u0 - mu; dy = u1 - mu;
    var = blockSum256(dx * dx + dy * dy, sred) * (1.f / 512.f);
    rs = rsqrtf(var + 1e-5f);
    float h0 = dx * rs * g1w[d0] + b1w[d0];
    float h1 = dy * rs * g1w[d0 + 1] + b1w[d0 + 1];
    ((float2*)(hout + (size_t)m * D_MODEL))[t] = make_float2(h0, h1);
    ((__half2*)(hh + (size_t)m * D_MODEL))[t] = __floats2half2_rn(h0, h1);
}

__global__ void __launch_bounds__(256) ln_final_kernel(
    const float* __restrict__ tin, const float* __restrict__ g2w,
    const float* __restrict__ b2w, float* __restrict__ out) {
    __shared__ float sred[8];
    int m = blockIdx.x, t = threadIdx.x;
    float2 v = ((const float2*)(tin + (size_t)m * D_MODEL))[t];
    float mu = blockSum256(v.x + v.y, sred) * (1.f / 512.f);
    float dx = v.x - mu, dy = v.y - mu;
    float var = blockSum256(dx * dx + dy * dy, sred) * (1.f / 512.f);
    float rs = rsqrtf(var + 1e-5f);
    int d0 = t * 2;
    int b = m >> 11;
    int s = m & (S_LEN - 1);
    float2 ov = make_float2(dx * rs * g2w[d0] + b2w[d0],
                            dy * rs * g2w[d0 + 1] + b2w[d0 + 1]);
    ((float2*)(out + ((size_t)(s * B_SZ + b)) * D_MODEL))[t] = ov;
}

// ---------------------------------------------------------------------------
// Launch
// ---------------------------------------------------------------------------
#define HSMEM_BN128 (STAGES * (128 + 128) * 64 * 2)   // 98304
#define HSMEM_BN64  (STAGES * (128 + 64) * 64 * 2)    // 73728

extern "C" void kernel_launch(void* const* d_in, const int* in_sizes, int n_in,
                              void* d_out, int out_size) {
    const float* src    = (const float*)d_in[0];
    const float* sph    = (const float*)d_in[1];
    const float* w_qs   = (const float*)d_in[2];
    const float* w_ks   = (const float*)d_in[3];
    const float* w_vs   = (const float*)d_in[4];
    const float* w_fc   = (const float*)d_in[5];
    const float* g_attn = (const float*)d_in[6];
    const float* b_attn = (const float*)d_in[7];
    const float* w1     = (const float*)d_in[8];
    const float* b1     = (const float*)d_in[9];
    const float* w2     = (const float*)d_in[10];
    const float* b2     = (const float*)d_in[11];
    const float* g1w    = (const float*)d_in[12];
    const float* bn1    = (const float*)d_in[13];
    const float* g2w    = (const float*)d_in[14];
    const float* bn2    = (const float*)d_in[15];

    float* out = (float*)d_out;
    float* p_out = out + OUT_ELEMS;

    void* sp = nullptr;
    cudaGetSymbolAddress(&sp, g_scratch);
    float* scr = (float*)sp;
    float* gt1 = scr + OFF_T1;
    float* gh  = scr + OFF_H;
    __half* xh   = (__half*)(scr + OFF_XH);
    __half* qh   = (__half*)(scr + OFF_QH);
    __half* kh   = (__half*)(scr + OFF_KH);
    __half* vt_h = (__half*)(scr + OFF_VTH);
    __half* gaoh = (__half*)(scr + OFF_GAOH);
    __half* hh   = (__half*)(scr + OFF_HH);
    __half* ffh  = (__half*)(scr + OFF_FFH);
    __half* wqh  = (__half*)(scr + OFF_WQH);
    __half* wkh  = (__half*)(scr + OFF_WKH);
    __half* wvh  = (__half*)(scr + OFF_WVH);
    __half* wfch = (__half*)(scr + OFF_WFCH);
    __half* w1h  = (__half*)(scr + OFF_W1H);
    __half* w2h  = (__half*)(scr + OFF_W2H);
    __half* s_h  = (__half*)(scr + OFF_SH);
    float2* part = (float2*)(scr + OFF_PART);

    cudaFuncSetAttribute(gemm_h<0, 128>,
                         cudaFuncAttributeMaxDynamicSharedMemorySize, HSMEM_BN128);
    cudaFuncSetAttribute(gemm_h<4, 64>,
                         cudaFuncAttributeMaxDynamicSharedMemorySize, HSMEM_BN64);
    cudaFuncSetAttribute(gemm_h<5, 128>,
                         cudaFuncAttributeMaxDynamicSharedMemorySize, HSMEM_BN128);
    cudaFuncSetAttribute(gemm_h<6, 64>,
                         cudaFuncAttributeMaxDynamicSharedMemorySize, HSMEM_BN64);

    // 0. fp16 conversions (src perm + all weights)
    convert_all<<<5120, 256>>>(src, w_qs, w_ks, w_vs, w_fc, w1, w2,
                               xh, wqh, wkh, wvh, wfch, w1h, w2h);

    // 1. fused QKV (fp16): z=0 Q, z=1 K, z=2 V^T
    dim3 gqkv(D_MODEL / 128, M_ROWS / 128, 3);
    gemm_h<0, 128><<<gqkv, 256, HSMEM_BN128>>>(
        xh, D_MODEL, wqh, wkh, wvh, D_MODEL, D_MODEL,
        nullptr, nullptr, nullptr, 0, qh);

    // 2. scores = (Q K^T) * 0.125 * sph -> fp16 + softmax partials
    dim3 gsc(S_LEN / 128, S_LEN / 128, B_SZ * H_HEADS);
    scores_f16<<<gsc, 256>>>(qh, kh, sph, s_h, part);

    // 3. fused softmax + PV -> p_out fp32 (streaming) + gaoh fp16
    softmax_pv<<<dim3(S_LEN / 64, B_SZ * H_HEADS), 256>>>(s_h, part, vt_h,
                                                          p_out, gaoh);

    // 4. fc projection + residual(src perm) -> gt1 fp32
    dim3 gfc(D_MODEL / 64, M_ROWS / 128, 1);
    gemm_h<4, 64><<<gfc, 256, HSMEM_BN64>>>(
        gaoh, D_MODEL, wfch, nullptr, nullptr, D_MODEL, D_MODEL,
        gt1, nullptr, src, D_MODEL, nullptr);

    // 5. double LayerNorm -> h fp32 + hh fp16
    ln_double_kernel<<<M_ROWS, 256>>>(gt1, src, g_attn, b_attn, g1w, bn1,
                                      gh, hh);

    // 6. FFN up: relu(h @ w1^T + b1) -> ffh fp16
    dim3 gffn(F_FFN / 128, M_ROWS / 128, 1);
    gemm_h<5, 128><<<gffn, 256, HSMEM_BN128>>>(
        hh, D_MODEL, w1h, nullptr, nullptr, D_MODEL, D_MODEL,
        nullptr, b1, nullptr, F_FFN, ffh);

    // 7. FFN down + b2 + residual(h) -> gt1 fp32
    gemm_h<6, 64><<<gfc, 256, HSMEM_BN64>>>(
        ffh, F_FFN, w2h, nullptr, nullptr, F_FFN, F_FFN,
        gt1, b2, gh, D_MODEL, nullptr);

    // 8. final LN + transposed store
    ln_final_kernel<<<M_ROWS, 256>>>(gt1, g2w, bn2, out);
}

// round 16
// speedup vs baseline: 1.8175x; 1.3232x over previous
#include <cuda_runtime.h>
#include <cuda_fp16.h>
#include <cstdint>
#include <cstddef>

// ---------------------------------------------------------------------------
// Problem constants
// ---------------------------------------------------------------------------
#define S_LEN 2048
#define B_SZ  2
#define D_MODEL 512
#define H_HEADS 8
#define DK 64
#define F_FFN 2048
#define M_ROWS (B_SZ * S_LEN)              // 4096
#define OUT_ELEMS (S_LEN * B_SZ * D_MODEL) // 2097152

// Scratch layout (float offsets)
#define OFF_T1   0                         // 2M floats
#define OFF_H    2097152                   // 2M floats
#define OFF_XH   4194304                   // 2M halves = 1M floats
#define OFF_QH   5242880                   // Q,K,VT each 2M halves = 1M floats
#define OFF_KH   6291456
#define OFF_VTH  7340032
#define OFF_GAOH 8388608                   // 1M floats
#define OFF_HH   9437184                   // 1M floats
#define OFF_FFH  10485760                  // 8M halves = 4M floats
#define OFF_WQH  14680064                  // 128K floats each
#define OFF_WKH  14811136
#define OFF_WVH  14942208
#define OFF_WFCH 15073280
#define OFF_W1H  15204352                  // 512K floats
#define OFF_W2H  15728640                  // 512K floats
#define OFF_SH   16252928                  // 67108864 halves = 33554432 floats
#define OFF_PART 49807360                  // 32768*32 float2 = 2097152 floats
#define SCRATCH_FLOATS 51904512

__device__ float g_scratch[SCRATCH_FLOATS];

// ---------------------------------------------------------------------------
// PTX helpers
// ---------------------------------------------------------------------------
__device__ __forceinline__ uint32_t smem_to_u32(const void* p) {
    uint32_t a;
    asm("{ .reg .u64 t; cvta.to.shared.u64 t, %1; cvt.u32.u64 %0, t; }"
        : "=r"(a) : "l"(p));
    return a;
}

#define CP_ASYNC16(dst, src) \
    asm volatile("cp.async.cg.shared.global [%0], [%1], 16;\n" \
                 :: "r"(dst), "l"(src))
#define CP_COMMIT() asm volatile("cp.async.commit_group;\n" ::: "memory")
#define CP_WAIT2()  asm volatile("cp.async.wait_group 2;\n" ::: "memory")
#define CP_WAIT1()  asm volatile("cp.async.wait_group 1;\n" ::: "memory")
#define CP_WAIT0()  asm volatile("cp.async.wait_group 0;\n" ::: "memory")

__device__ __forceinline__ void mma_f16(float (&dd)[4], const uint32_t (&a)[4],
                                        const uint32_t (&b)[2]) {
    asm volatile(
        "mma.sync.aligned.m16n8k16.row.col.f32.f16.f16.f32 "
        "{%0,%1,%2,%3}, {%4,%5,%6,%7}, {%8,%9}, {%0,%1,%2,%3};\n"
        : "+f"(dd[0]), "+f"(dd[1]), "+f"(dd[2]), "+f"(dd[3])
        : "r"(a[0]), "r"(a[1]), "r"(a[2]), "r"(a[3]), "r"(b[0]), "r"(b[1]));
}

// streaming fp32x4 store (evict-first)
__device__ __forceinline__ void stcs4(float* p, float4 v) {
    asm volatile("st.global.cs.v4.f32 [%0], {%1, %2, %3, %4};\n"
                 :: "l"(p), "f"(v.x), "f"(v.y), "f"(v.z), "f"(v.w) : "memory");
}

// permuted src row: x[m] = src[(s*B + b)] with m = b*S + s
__device__ __forceinline__ int perm_row(int m) {
    return ((m & (S_LEN - 1)) << 1) + (m >> 11);
}

// ---------------------------------------------------------------------------
// Conversion prep: src (permuted) + 6 weight matrices -> fp16
// ---------------------------------------------------------------------------
__global__ void __launch_bounds__(256) convert_all(
    const float* __restrict__ src,
    const float* __restrict__ wq, const float* __restrict__ wk,
    const float* __restrict__ wv, const float* __restrict__ wfc,
    const float* __restrict__ w1, const float* __restrict__ w2,
    __half* __restrict__ xh, __half* __restrict__ wqh, __half* __restrict__ wkh,
    __half* __restrict__ wvh, __half* __restrict__ wfch,
    __half* __restrict__ w1h, __half* __restrict__ w2h) {
    int i4 = blockIdx.x * 256 + threadIdx.x;   // float4 index
    if (i4 < 524288) {                          // xh with row permutation
        int m = i4 >> 7;
        int c = (i4 & 127) << 2;
        float4 v = *(const float4*)(src + (size_t)perm_row(m) * D_MODEL + c);
        __half2* d = (__half2*)(xh + (size_t)m * D_MODEL + c);
        d[0] = __floats2half2_rn(v.x, v.y);
        d[1] = __floats2half2_rn(v.z, v.w);
        return;
    }
    i4 -= 524288;
    const float* sp;
    __half* dp;
    if (i4 < 65536) { sp = wq; dp = wqh; }
    else if (i4 < 131072) { sp = wk; dp = wkh; i4 -= 65536; }
    else if (i4 < 196608) { sp = wv; dp = wvh; i4 -= 131072; }
    else if (i4 < 262144) { sp = wfc; dp = wfch; i4 -= 196608; }
    else if (i4 < 524288) { sp = w1; dp = w1h; i4 -= 262144; }
    else { sp = w2; dp = w2h; i4 -= 524288; }
    float4 v = *(const float4*)(sp + (size_t)i4 * 4);
    __half2* d = (__half2*)(dp + (size_t)i4 * 4);
    d[0] = __floats2half2_rn(v.x, v.y);
    d[1] = __floats2half2_rn(v.z, v.w);
}

// ---------------------------------------------------------------------------
// fp16 mma.sync GEMM: C[m,n] = sum_k A[m,k] * Bw[n,k]  (K-major halves)
// BM=128, BN template, BK=64, 3-stage cp.async ring, 256 threads (4m x 2n),
// 128-byte smem rows with conflict-free 8-chunk XOR swizzle.
//
// EPI: 0 = fused QKV (z selects B: B0/B1/B2; z<2 plain fp16, z=2 V^T scatter)
//      4 = fp32 out + resid(src perm)
//      5 = fp16 out relu(v + bias)
//      6 = fp32 out + bias + resid(fp32)
// ---------------------------------------------------------------------------
#define STAGES 3

template <int EPI, int BN>
__global__ void __launch_bounds__(256, 2) gemm_h(
    const __half* __restrict__ A, int lda,
    const __half* __restrict__ B0, const __half* __restrict__ B1,
    const __half* __restrict__ B2, int ldb,
    int K, float* __restrict__ C,
    const float* __restrict__ bias, const float* __restrict__ resid,
    int ldc, __half* __restrict__ Chalf) {
    constexpr int NT = BN / 16;
    constexpr int ASTG = 128 * 64;           // halves per A stage
    constexpr int BSTG = BN * 64;
    extern __shared__ __half hsm[];
    __half* smA = hsm;
    __half* smB = hsm + STAGES * ASTG;

    const int tid = threadIdx.x;
    const int w = tid >> 5, lane = tid & 31;
    const int g = lane >> 2, t = lane & 3;
    const int mw = w >> 1, nw = w & 1;
    const int m0 = blockIdx.y * 128, n0 = blockIdx.x * BN;
    const int z = blockIdx.z;

    const __half* Bp = (EPI == 0) ? ((z == 0) ? B0 : (z == 1) ? B1 : B2) : B0;

    const uint32_t sA = smem_to_u32(smA);
    const uint32_t sB = smem_to_u32(smB);

    float d[2][NT][4];
#pragma unroll
    for (int i = 0; i < 2; i++)
#pragma unroll
        for (int j = 0; j < NT; j++)
#pragma unroll
            for (int r = 0; r < 4; r++) d[i][j][r] = 0.f;

    const int NC = K >> 6;

    auto issue = [&](int kc, int stg) {
        int k0 = kc << 6;
#pragma unroll
        for (int i = 0; i < 4; i++) {
            int id = tid + (i << 8);          // 128 rows x 8 chunks
            int r = id >> 3, c = id & 7;
            uint32_t dst = sA + ((stg * ASTG + r * 64 + ((c ^ (r & 7)) << 3)) << 1);
            CP_ASYNC16(dst, A + (size_t)(m0 + r) * lda + k0 + (c << 3));
        }
#pragma unroll
        for (int i = 0; i < BN / 32; i++) {
            int id = tid + (i << 8);
            int r = id >> 3, c = id & 7;
            uint32_t dst = sB + ((stg * BSTG + r * 64 + ((c ^ (r & 7)) << 3)) << 1);
            CP_ASYNC16(dst, Bp + (size_t)(n0 + r) * ldb + k0 + (c << 3));
        }
        CP_COMMIT();
    };

    issue(0, 0);
    if (NC > 1) issue(1, 1);

    for (int kc = 0; kc < NC; kc++) {
        if (kc == NC - 1) { CP_WAIT0(); } else { CP_WAIT1(); }
        __syncthreads();
        if (kc + 2 < NC) issue(kc + 2, (kc + 2) % STAGES);

        int buf = kc % STAGES;
        const __half* Ab = smA + buf * ASTG;
        const __half* Bb = smB + buf * BSTG;
#pragma unroll
        for (int ks = 0; ks < 4; ks++) {
            const int lo = ((2 * ks) ^ g) * 8 + 2 * t;
            const int hi = ((2 * ks + 1) ^ g) * 8 + 2 * t;
            uint32_t a[2][4];
#pragma unroll
            for (int mtw = 0; mtw < 2; mtw++) {
                int r0 = (mw * 2 + mtw) * 16 + g;
                a[mtw][0] = *(const uint32_t*)(Ab + r0 * 64 + lo);
                a[mtw][1] = *(const uint32_t*)(Ab + (r0 + 8) * 64 + lo);
                a[mtw][2] = *(const uint32_t*)(Ab + r0 * 64 + hi);
                a[mtw][3] = *(const uint32_t*)(Ab + (r0 + 8) * 64 + hi);
            }
            uint32_t b[NT][2];
#pragma unroll
            for (int ntw = 0; ntw < NT; ntw++) {
                int nr = (nw * NT + ntw) * 8 + g;
                b[ntw][0] = *(const uint32_t*)(Bb + nr * 64 + lo);
                b[ntw][1] = *(const uint32_t*)(Bb + nr * 64 + hi);
            }
#pragma unroll
            for (int mtw = 0; mtw < 2; mtw++)
#pragma unroll
                for (int ntw = 0; ntw < NT; ntw++)
                    mma_f16(d[mtw][ntw], a[mtw], b[ntw]);
        }
        __syncthreads();
    }

    // ---------------- epilogue ----------------
#pragma unroll
    for (int mtw = 0; mtw < 2; mtw++)
#pragma unroll
        for (int ntw = 0; ntw < NT; ntw++)
#pragma unroll
            for (int half = 0; half < 2; half++) {
                int m = m0 + mw * 32 + mtw * 16 + half * 8 + g;
                int n = n0 + nw * (BN / 2) + ntw * 8 + t * 2;
                float v0 = d[mtw][ntw][half * 2 + 0];
                float v1 = d[mtw][ntw][half * 2 + 1];
                if (EPI == 0) {
                    if (z < 2) {          // Q/K fp16 plain (m, 512)
                        __half* dst = Chalf + (size_t)z * 2097152 +
                                      (size_t)m * D_MODEL + n;
                        *(__half2*)dst = __floats2half2_rn(v0, v1);
                    } else {              // V^T fp16 scatter to (b,h,dk,s)
                        int b = m >> 11, s = m & (S_LEN - 1);
                        int h = n >> 6, dd = n & 63;
                        __half* vt = Chalf + 2 * 2097152;
                        size_t base = ((size_t)((b << 3) + h) * DK + dd) * S_LEN + s;
                        vt[base] = __float2half(v0);
                        vt[base + S_LEN] = __float2half(v1);
                    }
                } else if (EPI == 4) {    // fp32 + resid(src perm)
                    size_t o = (size_t)m * ldc + n;
                    const float* rsrc = resid + (size_t)perm_row(m) * D_MODEL + n;
                    float2 rr = *(const float2*)rsrc;
                    *(float2*)(C + o) = make_float2(v0 + rr.x, v1 + rr.y);
                } else if (EPI == 5) {    // fp16 relu(v + bias)
                    size_t o = (size_t)m * ldc + n;
                    float2 bb = *(const float2*)(bias + n);
                    *(__half2*)(Chalf + o) =
                        __floats2half2_rn(fmaxf(v0 + bb.x, 0.f),
                                          fmaxf(v1 + bb.y, 0.f));
                } else {                  // fp32 + bias + resid
                    size_t o = (size_t)m * ldc + n;
                    float2 bb = *(const float2*)(bias + n);
                    float2 rr = *(const float2*)(resid + o);
                    *(float2*)(C + o) = make_float2(v0 + bb.x + rr.x,
                                                    v1 + bb.y + rr.y);
                }
            }
}

// ---------------------------------------------------------------------------
// Scores (fp16 x fp16): S[bh](m,n) = (Q K^T)(m,n) * 0.125 * sph -> fp16
// + per-(row, 64-col-tile) softmax partials (max, sum-exp) for split softmax.
// BM=BN=128, K=64 (single stage), 256 threads, 128B smem rows.
// (sph read via plain loads — evict-first was measured to amplify traffic.)
// ---------------------------------------------------------------------------
__global__ void __launch_bounds__(256, 2) scores_f16(
    const __half* __restrict__ qh, const __half* __restrict__ kh,
    const float* __restrict__ sph, __half* __restrict__ s_h,
    float2* __restrict__ part) {
    __shared__ __half sAm[128 * 64];
    __shared__ __half sBm[128 * 64];

    const int tid = threadIdx.x;
    const int w = tid >> 5, lane = tid & 31;
    const int g = lane >> 2, t = lane & 3;
    const int mw = w >> 1, nw = w & 1;
    const int m0 = blockIdx.y * 128, n0 = blockIdx.x * 128;
    const int bh = blockIdx.z;

    size_t hoff = (size_t)(bh >> 3) * (S_LEN * D_MODEL) + (size_t)(bh & 7) * DK;
    const __half* Ap = qh + hoff;
    const __half* Bp = kh + hoff;

    const uint32_t sA = smem_to_u32(sAm);
    const uint32_t sB = smem_to_u32(sBm);

#pragma unroll
    for (int i = 0; i < 4; i++) {
        int id = tid + (i << 8);
        int r = id >> 3, c = id & 7;
        uint32_t dst = sA + ((r * 64 + ((c ^ (r & 7)) << 3)) << 1);
        CP_ASYNC16(dst, Ap + (size_t)(m0 + r) * D_MODEL + (c << 3));
    }
#pragma unroll
    for (int i = 0; i < 4; i++) {
        int id = tid + (i << 8);
        int r = id >> 3, c = id & 7;
        uint32_t dst = sB + ((r * 64 + ((c ^ (r & 7)) << 3)) << 1);
        CP_ASYNC16(dst, Bp + (size_t)(n0 + r) * D_MODEL + (c << 3));
    }
    CP_COMMIT();
    CP_WAIT0();
    __syncthreads();

    float d[2][8][4];
#pragma unroll
    for (int i = 0; i < 2; i++)
#pragma unroll
        for (int j = 0; j < 8; j++)
#pragma unroll
            for (int r = 0; r < 4; r++) d[i][j][r] = 0.f;

#pragma unroll
    for (int ks = 0; ks < 4; ks++) {
        const int lo = ((2 * ks) ^ g) * 8 + 2 * t;
        const int hi = ((2 * ks + 1) ^ g) * 8 + 2 * t;
        uint32_t a[2][4];
#pragma unroll
        for (int mtw = 0; mtw < 2; mtw++) {
            int r0 = (mw * 2 + mtw) * 16 + g;
            a[mtw][0] = *(const uint32_t*)(sAm + r0 * 64 + lo);
            a[mtw][1] = *(const uint32_t*)(sAm + (r0 + 8) * 64 + lo);
            a[mtw][2] = *(const uint32_t*)(sAm + r0 * 64 + hi);
            a[mtw][3] = *(const uint32_t*)(sAm + (r0 + 8) * 64 + hi);
        }
        uint32_t b[8][2];
#pragma unroll
        for (int ntw = 0; ntw < 8; ntw++) {
            int nr = nw * 64 + ntw * 8 + g;
            b[ntw][0] = *(const uint32_t*)(sBm + nr * 64 + lo);
            b[ntw][1] = *(const uint32_t*)(sBm + nr * 64 + hi);
        }
#pragma unroll
        for (int mtw = 0; mtw < 2; mtw++)
#pragma unroll
            for (int ntw = 0; ntw < 8; ntw++)
                mma_f16(d[mtw][ntw], a[mtw], b[ntw]);
    }

    // epilogue: per row (mtw, half) -> store fp16 scores + tile partials
#pragma unroll
    for (int mtw = 0; mtw < 2; mtw++)
#pragma unroll
        for (int half = 0; half < 2; half++) {
            int m = m0 + mw * 32 + mtw * 16 + half * 8 + g;
            float tmp[16];
#pragma unroll
            for (int ntw = 0; ntw < 8; ntw++) {
                int n = n0 + nw * 64 + ntw * 8 + t * 2;
                size_t idx = ((size_t)bh * S_LEN + m) * S_LEN + n;
                float2 sp = *(const float2*)(sph + idx);
                float v0 = d[mtw][ntw][half * 2 + 0] * 0.125f * sp.x;
                float v1 = d[mtw][ntw][half * 2 + 1] * 0.125f * sp.y;
                __half2 h2 = __floats2half2_rn(v0, v1);
                *(__half2*)(s_h + idx) = h2;
                float2 fr = __half22float2(h2);
                tmp[ntw * 2] = fr.x;
                tmp[ntw * 2 + 1] = fr.y;
            }
            float mx = tmp[0];
#pragma unroll
            for (int i = 1; i < 16; i++) mx = fmaxf(mx, tmp[i]);
            mx = fmaxf(mx, __shfl_xor_sync(0xffffffffu, mx, 1));
            mx = fmaxf(mx, __shfl_xor_sync(0xffffffffu, mx, 2));
            float se = 0.f;
#pragma unroll
            for (int i = 0; i < 16; i++) se += __expf(tmp[i] - mx);
            se += __shfl_xor_sync(0xffffffffu, se, 1);
            se += __shfl_xor_sync(0xffffffffu, se, 2);
            if (t == 0) {
                int tile = blockIdx.x * 2 + nw;   // 32 tiles of 64 cols
                part[((size_t)bh * S_LEN + m) * 32 + tile] =
                    make_float2(mx, se);
            }
        }
}

// ---------------------------------------------------------------------------
// Fused softmax + PV without the p_h round-trip.
// One CTA: 64 q-rows of one (b,h). 3-stage cp.async ring; p_out via
// streaming stores (st.global.cs).
// ---------------------------------------------------------------------------
__global__ void __launch_bounds__(256) softmax_pv(
    const __half* __restrict__ s_h, const float2* __restrict__ part,
    const __half* __restrict__ vt, float* __restrict__ p_out,
    __half* __restrict__ gaoh) {
    __shared__ __half smA[3][64 * 64];
    __shared__ __half smB[3][64 * 64];
    __shared__ float rowM[64];
    __shared__ float rowInv[64];

    const int tid = threadIdx.x;
    const int w = tid >> 5, lane = tid & 31;
    const int bh = blockIdx.y;
    const int m0 = blockIdx.x * 64;

    // ---------------- phase 0: global (M, 1/S) per row ----------------
    {
        const float2* pbase = part + ((size_t)bh * S_LEN + m0) * 32;
#pragma unroll
        for (int rr = 0; rr < 8; rr++) {
            int r = w * 8 + rr;
            float2 pm = pbase[(size_t)r * 32 + lane];   // lane = tile 0..31
            float M = pm.x;
#pragma unroll
            for (int o = 16; o; o >>= 1)
                M = fmaxf(M, __shfl_xor_sync(0xffffffffu, M, o));
            float contrib = pm.y * __expf(pm.x - M);
#pragma unroll
            for (int o = 16; o; o >>= 1)
                contrib += __shfl_xor_sync(0xffffffffu, contrib, o);
            if (lane == 0) {
                rowM[r] = M;
                rowInv[r] = 1.0f / contrib;
            }
        }
    }
    __syncthreads();

    // ---------------- phase 2: normalize + p_out + PV ----------------
    const int g = lane >> 2, t = lane & 3;
    const int mw = w >> 1, nw = w & 1;

    const __half* Ap = s_h + ((size_t)bh * S_LEN + m0) * S_LEN;
    float* Pp = p_out + ((size_t)bh * S_LEN + m0) * S_LEN;
    const __half* Bp = vt + (size_t)bh * DK * S_LEN;
    const uint32_t sA = smem_to_u32(smA);
    const uint32_t sB = smem_to_u32(smB);

    float d[4][4];
#pragma unroll
    for (int j = 0; j < 4; j++)
#pragma unroll
        for (int r = 0; r < 4; r++) d[j][r] = 0.f;

    const int NC = S_LEN / 64;   // 32

    auto issue = [&](int kc, int stg) {
        int k0 = kc << 6;
#pragma unroll
        for (int i = 0; i < 2; i++) {
            int id = tid + (i << 8);
            int r = id >> 3, c = id & 7;
            uint32_t dst = sA + ((stg * 4096 + r * 64 + ((c ^ (r & 7)) << 3)) << 1);
            CP_ASYNC16(dst, Ap + (size_t)r * S_LEN + k0 + (c << 3));
        }
#pragma unroll
        for (int i = 0; i < 2; i++) {
            int id = tid + (i << 8);
            int r = id >> 3, c = id & 7;
            uint32_t dst = sB + ((stg * 4096 + r * 64 + ((c ^ (r & 7)) << 3)) << 1);
            CP_ASYNC16(dst, Bp + (size_t)r * S_LEN + k0 + (c << 3));
        }
        CP_COMMIT();
    };

    issue(0, 0);
    if (NC > 1) issue(1, 1);
    for (int kc = 0; kc < NC; kc++) {
        int k0 = kc << 6;
        if (kc + 2 < NC) {
            issue(kc + 2, (kc + 2) % 3);
            CP_WAIT2();
        } else if (kc + 1 < NC) {
            CP_WAIT1();
        } else {
            CP_WAIT0();
        }
        __syncthreads();
        int buf = kc % 3;
        __half* Ab = smA[buf];
        const __half* Bb = smB[buf];

        // normalize chunk in place + write fp32 p_attn (streaming)
#pragma unroll
        for (int i = 0; i < 2; i++) {
            int id = tid + (i << 8);
            int r = id >> 3, c = id & 7;
            __half* sp = Ab + r * 64 + ((c ^ (r & 7)) << 3);
            uint4 raw = *(const uint4*)sp;
            const __half2* h2 = (const __half2*)&raw;
            float M = rowM[r], inv = rowInv[r];
            float p[8];
#pragma unroll
            for (int j = 0; j < 4; j++) {
                float2 f = __half22float2(h2[j]);
                p[2 * j] = __expf(f.x - M) * inv;
                p[2 * j + 1] = __expf(f.y - M) * inv;
            }
            float* pd = Pp + (size_t)r * S_LEN + k0 + (c << 3);
            stcs4(pd, make_float4(p[0], p[1], p[2], p[3]));
            stcs4(pd + 4, make_float4(p[4], p[5], p[6], p[7]));
            uint4 pk;
            __half2* pk2 = (__half2*)&pk;
#pragma unroll
            for (int j = 0; j < 4; j++)
                pk2[j] = __floats2half2_rn(p[2 * j], p[2 * j + 1]);
            *(uint4*)sp = pk;
        }
        __syncthreads();

        // PV MMA on normalized tile
#pragma unroll
        for (int ks = 0; ks < 4; ks++) {
            const int lo = ((2 * ks) ^ g) * 8 + 2 * t;
            const int hi = ((2 * ks + 1) ^ g) * 8 + 2 * t;
            uint32_t a[4];
            {
                int r0 = mw * 16 + g;
                a[0] = *(const uint32_t*)(Ab + r0 * 64 + lo);
                a[1] = *(const uint32_t*)(Ab + (r0 + 8) * 64 + lo);
                a[2] = *(const uint32_t*)(Ab + r0 * 64 + hi);
                a[3] = *(const uint32_t*)(Ab + (r0 + 8) * 64 + hi);
            }
            uint32_t b[4][2];
#pragma unroll
            for (int ntw = 0; ntw < 4; ntw++) {
                int nr = nw * 32 + ntw * 8 + g;
                b[ntw][0] = *(const uint32_t*)(Bb + nr * 64 + lo);
                b[ntw][1] = *(const uint32_t*)(Bb + nr * 64 + hi);
            }
#pragma unroll
            for (int ntw = 0; ntw < 4; ntw++)
                mma_f16(d[ntw], a, b[ntw]);
        }
        __syncthreads();
    }

    int b = bh >> 3, h = bh & 7;
#pragma unroll
    for (int ntw = 0; ntw < 4; ntw++)
#pragma unroll
        for (int half = 0; half < 2; half++) {
            int m = m0 + mw * 16 + half * 8 + g;
            int n = nw * 32 + ntw * 8 + t * 2;
            size_t dst = ((size_t)(b * S_LEN + m)) * D_MODEL + h * DK + n;
            *(__half2*)(gaoh + dst) =
                __floats2half2_rn(d[ntw][half * 2 + 0], d[ntw][half * 2 + 1]);
        }
}

// ---------------------------------------------------------------------------
// LayerNorm kernels
// ---------------------------------------------------------------------------
__device__ __forceinline__ float blockSum256(float v, float* sred) {
#pragma unroll
    for (int o = 16; o; o >>= 1) v += __shfl_xor_sync(0xffffffffu, v, o);
    __syncthreads();
    if ((threadIdx.x & 31) == 0) sred[threadIdx.x >> 5] = v;
    __syncthreads();
    float s = sred[0];
#pragma unroll
    for (int i = 1; i < 8; i++) s += sred[i];
    return s;
}

__global__ void __launch_bounds__(256) ln_double_kernel(
    const float* __restrict__ tin, const float* __restrict__ src,
    const float* __restrict__ ga, const float* __restrict__ ba,
    const float* __restrict__ g1w, const float* __restrict__ b1w,
    float* __restrict__ hout, __half* __restrict__ hh) {
    __shared__ float sred[8];
    int m = blockIdx.x, t = threadIdx.x;
    float2 v = ((const float2*)(tin + (size_t)m * D_MODEL))[t];
    float2 xv = ((const float2*)(src + (size_t)perm_row(m) * D_MODEL))[t];
    float mu = blockSum256(v.x + v.y, sred) * (1.f / 512.f);
    float dx = v.x - mu, dy = v.y - mu;
    float var = blockSum256(dx * dx + dy * dy, sred) * (1.f / 512.f);
    float rs = rsqrtf(var + 1e-6f);
    int d0 = t * 2;
    float u0 = xv.x + dx * rs * ga[d0] + ba[d0];
    float u1 = xv.y + dy * rs * ga[d0 + 1] + ba[d0 + 1];
    mu = blockSum256(u0 + u1, sred) * (1.f / 512.f);
    dx = u0 - mu; dy = u1 - mu;
    var = blockSum256(dx * dx + dy * dy, sred) * (1.f / 512.f);
    rs = rsqrtf(var + 1e-5f);
    float h0 = dx * rs * g1w[d0] + b1w[d0];
    float h1 = dy * rs * g1w[d0 + 1] + b1w[d0 + 1];
    ((float2*)(hout + (size_t)m * D_MODEL))[t] = make_float2(h0, h1);
    ((__half2*)(hh + (size_t)m * D_MODEL))[t] = __floats2half2_rn(h0, h1);
}

__global__ void __launch_bounds__(256) ln_final_kernel(
    const float* __restrict__ tin, const float* __restrict__ g2w,
    const float* __restrict__ b2w, float* __restrict__ out) {
    __shared__ float sred[8];
    int m = blockIdx.x, t = threadIdx.x;
    float2 v = ((const float2*)(tin + (size_t)m * D_MODEL))[t];
    float mu = blockSum256(v.x + v.y, sred) * (1.f / 512.f);
    float dx = v.x - mu, dy = v.y - mu;
    float var = blockSum256(dx * dx + dy * dy, sred) * (1.f / 512.f);
    float rs = rsqrtf(var + 1e-5f);
    int d0 = t * 2;
    int b = m >> 11;
    int s = m & (S_LEN - 1);
    float2 ov = make_float2(dx * rs * g2w[d0] + b2w[d0],
                            dy * rs * g2w[d0 + 1] + b2w[d0 + 1]);
    ((float2*)(out + ((size_t)(s * B_SZ + b)) * D_MODEL))[t] = ov;
}

// ---------------------------------------------------------------------------
// Launch
// ---------------------------------------------------------------------------
#define HSMEM_BN128 (STAGES * (128 + 128) * 64 * 2)   // 98304
#define HSMEM_BN64  (STAGES * (128 + 64) * 64 * 2)    // 73728

extern "C" void kernel_launch(void* const* d_in, const int* in_sizes, int n_in,
                              void* d_out, int out_size) {
    const float* src    = (const float*)d_in[0];
    const float* sph    = (const float*)d_in[1];
    const float* w_qs   = (const float*)d_in[2];
    const float* w_ks   = (const float*)d_in[3];
    const float* w_vs   = (const float*)d_in[4];
    const float* w_fc   = (const float*)d_in[5];
    const float* g_attn = (const float*)d_in[6];
    const float* b_attn = (const float*)d_in[7];
    const float* w1     = (const float*)d_in[8];
    const float* b1     = (const float*)d_in[9];
    const float* w2     = (const float*)d_in[10];
    const float* b2     = (const float*)d_in[11];
    const float* g1w    = (const float*)d_in[12];
    const float* bn1    = (const float*)d_in[13];
    const float* g2w    = (const float*)d_in[14];
    const float* bn2    = (const float*)d_in[15];

    float* out = (float*)d_out;
    float* p_out = out + OUT_ELEMS;

    void* sp = nullptr;
    cudaGetSymbolAddress(&sp, g_scratch);
    float* scr = (float*)sp;
    float* gt1 = scr + OFF_T1;
    float* gh  = scr + OFF_H;
    __half* xh   = (__half*)(scr + OFF_XH);
    __half* qh   = (__half*)(scr + OFF_QH);
    __half* kh   = (__half*)(scr + OFF_KH);
    __half* vt_h = (__half*)(scr + OFF_VTH);
    __half* gaoh = (__half*)(scr + OFF_GAOH);
    __half* hh   = (__half*)(scr + OFF_HH);
    __half* ffh  = (__half*)(scr + OFF_FFH);
    __half* wqh  = (__half*)(scr + OFF_WQH);
    __half* wkh  = (__half*)(scr + OFF_WKH);
    __half* wvh  = (__half*)(scr + OFF_WVH);
    __half* wfch = (__half*)(scr + OFF_WFCH);
    __half* w1h  = (__half*)(scr + OFF_W1H);
    __half* w2h  = (__half*)(scr + OFF_W2H);
    __half* s_h  = (__half*)(scr + OFF_SH);
    float2* part = (float2*)(scr + OFF_PART);

    cudaFuncSetAttribute(gemm_h<0, 128>,
                         cudaFuncAttributeMaxDynamicSharedMemorySize, HSMEM_BN128);
    cudaFuncSetAttribute(gemm_h<4, 64>,
                         cudaFuncAttributeMaxDynamicSharedMemorySize, HSMEM_BN64);
    cudaFuncSetAttribute(gemm_h<5, 128>,
                         cudaFuncAttributeMaxDynamicSharedMemorySize, HSMEM_BN128);
    cudaFuncSetAttribute(gemm_h<6, 64>,
                         cudaFuncAttributeMaxDynamicSharedMemorySize, HSMEM_BN64);

    // 0. fp16 conversions (src perm + all weights)
    convert_all<<<5120, 256>>>(src, w_qs, w_ks, w_vs, w_fc, w1, w2,
                               xh, wqh, wkh, wvh, wfch, w1h, w2h);

    // 1. fused QKV (fp16): z=0 Q, z=1 K, z=2 V^T
    dim3 gqkv(D_MODEL / 128, M_ROWS / 128, 3);
    gemm_h<0, 128><<<gqkv, 256, HSMEM_BN128>>>(
        xh, D_MODEL, wqh, wkh, wvh, D_MODEL, D_MODEL,
        nullptr, nullptr, nullptr, 0, qh);

    // 2. scores = (Q K^T) * 0.125 * sph -> fp16 + softmax partials
    dim3 gsc(S_LEN / 128, S_LEN / 128, B_SZ * H_HEADS);
    scores_f16<<<gsc, 256>>>(qh, kh, sph, s_h, part);

    // 3. fused softmax + PV -> p_out fp32 (streaming) + gaoh fp16
    softmax_pv<<<dim3(S_LEN / 64, B_SZ * H_HEADS), 256>>>(s_h, part, vt_h,
                                                          p_out, gaoh);

    // 4. fc projection + residual(src perm) -> gt1 fp32
    dim3 gfc(D_MODEL / 64, M_ROWS / 128, 1);
    gemm_h<4, 64><<<gfc, 256, HSMEM_BN64>>>(
        gaoh, D_MODEL, wfch, nullptr, nullptr, D_MODEL, D_MODEL,
        gt1, nullptr, src, D_MODEL, nullptr);

    // 5. double LayerNorm -> h fp32 + hh fp16
    ln_double_kernel<<<M_ROWS, 256>>>(gt1, src, g_attn, b_attn, g1w, bn1,
                                      gh, hh);

    // 6. FFN up: relu(h @ w1^T + b1) -> ffh fp16
    dim3 gffn(F_FFN / 128, M_ROWS / 128, 1);
    gemm_h<5, 128><<<gffn, 256, HSMEM_BN128>>>(
        hh, D_MODEL, w1h, nullptr, nullptr, D_MODEL, D_MODEL,
        nullptr, b1, nullptr, F_FFN, ffh);

    // 7. FFN down + b2 + residual(h) -> gt1 fp32
    gemm_h<6, 64><<<gfc, 256, HSMEM_BN64>>>(
        ffh, F_FFN, w2h, nullptr, nullptr, F_FFN, F_FFN,
        gt1, b2, gh, D_MODEL, nullptr);

    // 8. final LN + transposed store
    ln_final_kernel<<<M_ROWS, 256>>>(gt1, g2w, bn2, out);
}

// round 17
// speedup vs baseline: 1.8302x; 1.0070x over previous
#include <cuda_runtime.h>
#include <cuda_fp16.h>
#include <cstdint>
#include <cstddef>

// ---------------------------------------------------------------------------
// Problem constants
// ---------------------------------------------------------------------------
#define S_LEN 2048
#define B_SZ  2
#define D_MODEL 512
#define H_HEADS 8
#define DK 64
#define F_FFN 2048
#define M_ROWS (B_SZ * S_LEN)              // 4096
#define OUT_ELEMS (S_LEN * B_SZ * D_MODEL) // 2097152

// Scratch layout (float offsets)
#define OFF_T1   0                         // 2M floats
#define OFF_H    2097152                   // 2M floats
#define OFF_XH   4194304                   // 2M halves = 1M floats
#define OFF_QH   5242880                   // Q,K,VT each 2M halves = 1M floats
#define OFF_KH   6291456
#define OFF_VTH  7340032
#define OFF_GAOH 8388608                   // 1M floats
#define OFF_HH   9437184                   // 1M floats
#define OFF_FFH  10485760                  // 8M halves = 4M floats
#define OFF_WQH  14680064                  // 128K floats each
#define OFF_WKH  14811136
#define OFF_WVH  14942208
#define OFF_WFCH 15073280
#define OFF_W1H  15204352                  // 512K floats
#define OFF_W2H  15728640                  // 512K floats
#define OFF_SH   16252928                  // 67108864 halves = 33554432 floats
#define OFF_PART 49807360                  // 32768*32 float2 = 2097152 floats
#define SCRATCH_FLOATS 51904512

__device__ float g_scratch[SCRATCH_FLOATS];

// ---------------------------------------------------------------------------
// PTX helpers
// ---------------------------------------------------------------------------
__device__ __forceinline__ uint32_t smem_to_u32(const void* p) {
    uint32_t a;
    asm("{ .reg .u64 t; cvta.to.shared.u64 t, %1; cvt.u32.u64 %0, t; }"
        : "=r"(a) : "l"(p));
    return a;
}

#define CP_ASYNC16(dst, src) \
    asm volatile("cp.async.cg.shared.global [%0], [%1], 16;\n" \
                 :: "r"(dst), "l"(src))
#define CP_COMMIT() asm volatile("cp.async.commit_group;\n" ::: "memory")
#define CP_WAIT2()  asm volatile("cp.async.wait_group 2;\n" ::: "memory")
#define CP_WAIT1()  asm volatile("cp.async.wait_group 1;\n" ::: "memory")
#define CP_WAIT0()  asm volatile("cp.async.wait_group 0;\n" ::: "memory")

__device__ __forceinline__ void mma_f16(float (&dd)[4], const uint32_t (&a)[4],
                                        const uint32_t (&b)[2]) {
    asm volatile(
        "mma.sync.aligned.m16n8k16.row.col.f32.f16.f16.f32 "
        "{%0,%1,%2,%3}, {%4,%5,%6,%7}, {%8,%9}, {%0,%1,%2,%3};\n"
        : "+f"(dd[0]), "+f"(dd[1]), "+f"(dd[2]), "+f"(dd[3])
        : "r"(a[0]), "r"(a[1]), "r"(a[2]), "r"(a[3]), "r"(b[0]), "r"(b[1]));
}

// streaming fp32x4 store (evict-first)
__device__ __forceinline__ void stcs4(float* p, float4 v) {
    asm volatile("st.global.cs.v4.f32 [%0], {%1, %2, %3, %4};\n"
                 :: "l"(p), "f"(v.x), "f"(v.y), "f"(v.z), "f"(v.w) : "memory");
}

// permuted src row: x[m] = src[(s*B + b)] with m = b*S + s
__device__ __forceinline__ int perm_row(int m) {
    return ((m & (S_LEN - 1)) << 1) + (m >> 11);
}

// ---------------------------------------------------------------------------
// Conversion prep: src (permuted) + 6 weight matrices -> fp16
// ---------------------------------------------------------------------------
__global__ void __launch_bounds__(256) convert_all(
    const float* __restrict__ src,
    const float* __restrict__ wq, const float* __restrict__ wk,
    const float* __restrict__ wv, const float* __restrict__ wfc,
    const float* __restrict__ w1, const float* __restrict__ w2,
    __half* __restrict__ xh, __half* __restrict__ wqh, __half* __restrict__ wkh,
    __half* __restrict__ wvh, __half* __restrict__ wfch,
    __half* __restrict__ w1h, __half* __restrict__ w2h) {
    int i4 = blockIdx.x * 256 + threadIdx.x;   // float4 index
    if (i4 < 524288) {                          // xh with row permutation
        int m = i4 >> 7;
        int c = (i4 & 127) << 2;
        float4 v = *(const float4*)(src + (size_t)perm_row(m) * D_MODEL + c);
        __half2* d = (__half2*)(xh + (size_t)m * D_MODEL + c);
        d[0] = __floats2half2_rn(v.x, v.y);
        d[1] = __floats2half2_rn(v.z, v.w);
        return;
    }
    i4 -= 524288;
    const float* sp;
    __half* dp;
    if (i4 < 65536) { sp = wq; dp = wqh; }
    else if (i4 < 131072) { sp = wk; dp = wkh; i4 -= 65536; }
    else if (i4 < 196608) { sp = wv; dp = wvh; i4 -= 131072; }
    else if (i4 < 262144) { sp = wfc; dp = wfch; i4 -= 196608; }
    else if (i4 < 524288) { sp = w1; dp = w1h; i4 -= 262144; }
    else { sp = w2; dp = w2h; i4 -= 524288; }
    float4 v = *(const float4*)(sp + (size_t)i4 * 4);
    __half2* d = (__half2*)(dp + (size_t)i4 * 4);
    d[0] = __floats2half2_rn(v.x, v.y);
    d[1] = __floats2half2_rn(v.z, v.w);
}

// ---------------------------------------------------------------------------
// fp16 mma.sync GEMM: C[m,n] = sum_k A[m,k] * Bw[n,k]  (K-major halves)
// BM=128, BN template, BK=64, 3-stage cp.async ring, 256 threads (4m x 2n),
// 128-byte smem rows with conflict-free 8-chunk XOR swizzle.
//
// EPI: 0 = fused QKV (z selects B: B0/B1/B2; z<2 plain fp16, z=2 V^T scatter)
//      4 = fp32 out + resid(src perm)
//      5 = fp16 out relu(v + bias)
//      6 = fp32 out + bias + resid(fp32)
// ---------------------------------------------------------------------------
#define STAGES 3

template <int EPI, int BN>
__global__ void __launch_bounds__(256, 2) gemm_h(
    const __half* __restrict__ A, int lda,
    const __half* __restrict__ B0, const __half* __restrict__ B1,
    const __half* __restrict__ B2, int ldb,
    int K, float* __restrict__ C,
    const float* __restrict__ bias, const float* __restrict__ resid,
    int ldc, __half* __restrict__ Chalf) {
    constexpr int NT = BN / 16;
    constexpr int ASTG = 128 * 64;           // halves per A stage
    constexpr int BSTG = BN * 64;
    extern __shared__ __half hsm[];
    __half* smA = hsm;
    __half* smB = hsm + STAGES * ASTG;

    const int tid = threadIdx.x;
    const int w = tid >> 5, lane = tid & 31;
    const int g = lane >> 2, t = lane & 3;
    const int mw = w >> 1, nw = w & 1;
    const int m0 = blockIdx.y * 128, n0 = blockIdx.x * BN;
    const int z = blockIdx.z;

    const __half* Bp = (EPI == 0) ? ((z == 0) ? B0 : (z == 1) ? B1 : B2) : B0;

    const uint32_t sA = smem_to_u32(smA);
    const uint32_t sB = smem_to_u32(smB);

    float d[2][NT][4];
#pragma unroll
    for (int i = 0; i < 2; i++)
#pragma unroll
        for (int j = 0; j < NT; j++)
#pragma unroll
            for (int r = 0; r < 4; r++) d[i][j][r] = 0.f;

    const int NC = K >> 6;

    auto issue = [&](int kc, int stg) {
        int k0 = kc << 6;
#pragma unroll
        for (int i = 0; i < 4; i++) {
            int id = tid + (i << 8);          // 128 rows x 8 chunks
            int r = id >> 3, c = id & 7;
            uint32_t dst = sA + ((stg * ASTG + r * 64 + ((c ^ (r & 7)) << 3)) << 1);
            CP_ASYNC16(dst, A + (size_t)(m0 + r) * lda + k0 + (c << 3));
        }
#pragma unroll
        for (int i = 0; i < BN / 32; i++) {
            int id = tid + (i << 8);
            int r = id >> 3, c = id & 7;
            uint32_t dst = sB + ((stg * BSTG + r * 64 + ((c ^ (r & 7)) << 3)) << 1);
            CP_ASYNC16(dst, Bp + (size_t)(n0 + r) * ldb + k0 + (c << 3));
        }
        CP_COMMIT();
    };

    issue(0, 0);
    if (NC > 1) issue(1, 1);

    for (int kc = 0; kc < NC; kc++) {
        if (kc == NC - 1) { CP_WAIT0(); } else { CP_WAIT1(); }
        __syncthreads();
        if (kc + 2 < NC) issue(kc + 2, (kc + 2) % STAGES);

        int buf = kc % STAGES;
        const __half* Ab = smA + buf * ASTG;
        const __half* Bb = smB + buf * BSTG;
#pragma unroll
        for (int ks = 0; ks < 4; ks++) {
            const int lo = ((2 * ks) ^ g) * 8 + 2 * t;
            const int hi = ((2 * ks + 1) ^ g) * 8 + 2 * t;
            uint32_t a[2][4];
#pragma unroll
            for (int mtw = 0; mtw < 2; mtw++) {
                int r0 = (mw * 2 + mtw) * 16 + g;
                a[mtw][0] = *(const uint32_t*)(Ab + r0 * 64 + lo);
                a[mtw][1] = *(const uint32_t*)(Ab + (r0 + 8) * 64 + lo);
                a[mtw][2] = *(const uint32_t*)(Ab + r0 * 64 + hi);
                a[mtw][3] = *(const uint32_t*)(Ab + (r0 + 8) * 64 + hi);
            }
            uint32_t b[NT][2];
#pragma unroll
            for (int ntw = 0; ntw < NT; ntw++) {
                int nr = (nw * NT + ntw) * 8 + g;
                b[ntw][0] = *(const uint32_t*)(Bb + nr * 64 + lo);
                b[ntw][1] = *(const uint32_t*)(Bb + nr * 64 + hi);
            }
#pragma unroll
            for (int mtw = 0; mtw < 2; mtw++)
#pragma unroll
                for (int ntw = 0; ntw < NT; ntw++)
                    mma_f16(d[mtw][ntw], a[mtw], b[ntw]);
        }
        __syncthreads();
    }

    // ---------------- epilogue ----------------
#pragma unroll
    for (int mtw = 0; mtw < 2; mtw++)
#pragma unroll
        for (int ntw = 0; ntw < NT; ntw++)
#pragma unroll
            for (int half = 0; half < 2; half++) {
                int m = m0 + mw * 32 + mtw * 16 + half * 8 + g;
                int n = n0 + nw * (BN / 2) + ntw * 8 + t * 2;
                float v0 = d[mtw][ntw][half * 2 + 0];
                float v1 = d[mtw][ntw][half * 2 + 1];
                if (EPI == 0) {
                    if (z < 2) {          // Q/K fp16 plain (m, 512)
                        __half* dst = Chalf + (size_t)z * 2097152 +
                                      (size_t)m * D_MODEL + n;
                        *(__half2*)dst = __floats2half2_rn(v0, v1);
                    } else {              // V^T fp16 scatter to (b,h,dk,s)
                        int b = m >> 11, s = m & (S_LEN - 1);
                        int h = n >> 6, dd = n & 63;
                        __half* vt = Chalf + 2 * 2097152;
                        size_t base = ((size_t)((b << 3) + h) * DK + dd) * S_LEN + s;
                        vt[base] = __float2half(v0);
                        vt[base + S_LEN] = __float2half(v1);
                    }
                } else if (EPI == 4) {    // fp32 + resid(src perm)
                    size_t o = (size_t)m * ldc + n;
                    const float* rsrc = resid + (size_t)perm_row(m) * D_MODEL + n;
                    float2 rr = *(const float2*)rsrc;
                    *(float2*)(C + o) = make_float2(v0 + rr.x, v1 + rr.y);
                } else if (EPI == 5) {    // fp16 relu(v + bias)
                    size_t o = (size_t)m * ldc + n;
                    float2 bb = *(const float2*)(bias + n);
                    *(__half2*)(Chalf + o) =
                        __floats2half2_rn(fmaxf(v0 + bb.x, 0.f),
                                          fmaxf(v1 + bb.y, 0.f));
                } else {                  // fp32 + bias + resid
                    size_t o = (size_t)m * ldc + n;
                    float2 bb = *(const float2*)(bias + n);
                    float2 rr = *(const float2*)(resid + o);
                    *(float2*)(C + o) = make_float2(v0 + bb.x + rr.x,
                                                    v1 + bb.y + rr.y);
                }
            }
}

// ---------------------------------------------------------------------------
// Scores (fp16 x fp16): S[bh](m,n) = (Q K^T)(m,n) * 0.125 * sph -> fp16
// + per-(row, 64-col-tile) softmax partials (max, sum-exp) for split softmax.
// BM=BN=128, K=64 (single stage), 256 threads, 128B smem rows.
// ---------------------------------------------------------------------------
__global__ void __launch_bounds__(256, 2) scores_f16(
    const __half* __restrict__ qh, const __half* __restrict__ kh,
    const float* __restrict__ sph, __half* __restrict__ s_h,
    float2* __restrict__ part) {
    __shared__ __half sAm[128 * 64];
    __shared__ __half sBm[128 * 64];

    const int tid = threadIdx.x;
    const int w = tid >> 5, lane = tid & 31;
    const int g = lane >> 2, t = lane & 3;
    const int mw = w >> 1, nw = w & 1;
    const int m0 = blockIdx.y * 128, n0 = blockIdx.x * 128;
    const int bh = blockIdx.z;

    size_t hoff = (size_t)(bh >> 3) * (S_LEN * D_MODEL) + (size_t)(bh & 7) * DK;
    const __half* Ap = qh + hoff;
    const __half* Bp = kh + hoff;

    const uint32_t sA = smem_to_u32(sAm);
    const uint32_t sB = smem_to_u32(sBm);

#pragma unroll
    for (int i = 0; i < 4; i++) {
        int id = tid + (i << 8);
        int r = id >> 3, c = id & 7;
        uint32_t dst = sA + ((r * 64 + ((c ^ (r & 7)) << 3)) << 1);
        CP_ASYNC16(dst, Ap + (size_t)(m0 + r) * D_MODEL + (c << 3));
    }
#pragma unroll
    for (int i = 0; i < 4; i++) {
        int id = tid + (i << 8);
        int r = id >> 3, c = id & 7;
        uint32_t dst = sB + ((r * 64 + ((c ^ (r & 7)) << 3)) << 1);
        CP_ASYNC16(dst, Bp + (size_t)(n0 + r) * D_MODEL + (c << 3));
    }
    CP_COMMIT();
    CP_WAIT0();
    __syncthreads();

    float d[2][8][4];
#pragma unroll
    for (int i = 0; i < 2; i++)
#pragma unroll
        for (int j = 0; j < 8; j++)
#pragma unroll
            for (int r = 0; r < 4; r++) d[i][j][r] = 0.f;

#pragma unroll
    for (int ks = 0; ks < 4; ks++) {
        const int lo = ((2 * ks) ^ g) * 8 + 2 * t;
        const int hi = ((2 * ks + 1) ^ g) * 8 + 2 * t;
        uint32_t a[2][4];
#pragma unroll
        for (int mtw = 0; mtw < 2; mtw++) {
            int r0 = (mw * 2 + mtw) * 16 + g;
            a[mtw][0] = *(const uint32_t*)(sAm + r0 * 64 + lo);
            a[mtw][1] = *(const uint32_t*)(sAm + (r0 + 8) * 64 + lo);
            a[mtw][2] = *(const uint32_t*)(sAm + r0 * 64 + hi);
            a[mtw][3] = *(const uint32_t*)(sAm + (r0 + 8) * 64 + hi);
        }
        uint32_t b[8][2];
#pragma unroll
        for (int ntw = 0; ntw < 8; ntw++) {
            int nr = nw * 64 + ntw * 8 + g;
            b[ntw][0] = *(const uint32_t*)(sBm + nr * 64 + lo);
            b[ntw][1] = *(const uint32_t*)(sBm + nr * 64 + hi);
        }
#pragma unroll
        for (int mtw = 0; mtw < 2; mtw++)
#pragma unroll
            for (int ntw = 0; ntw < 8; ntw++)
                mma_f16(d[mtw][ntw], a[mtw], b[ntw]);
    }

    // epilogue: per row (mtw, half) -> store fp16 scores + tile partials
#pragma unroll
    for (int mtw = 0; mtw < 2; mtw++)
#pragma unroll
        for (int half = 0; half < 2; half++) {
            int m = m0 + mw * 32 + mtw * 16 + half * 8 + g;
            float tmp[16];
#pragma unroll
            for (int ntw = 0; ntw < 8; ntw++) {
                int n = n0 + nw * 64 + ntw * 8 + t * 2;
                size_t idx = ((size_t)bh * S_LEN + m) * S_LEN + n;
                float2 sp = *(const float2*)(sph + idx);
                float v0 = d[mtw][ntw][half * 2 + 0] * 0.125f * sp.x;
                float v1 = d[mtw][ntw][half * 2 + 1] * 0.125f * sp.y;
                __half2 h2 = __floats2half2_rn(v0, v1);
                *(__half2*)(s_h + idx) = h2;
                float2 fr = __half22float2(h2);
                tmp[ntw * 2] = fr.x;
                tmp[ntw * 2 + 1] = fr.y;
            }
            float mx = tmp[0];
#pragma unroll
            for (int i = 1; i < 16; i++) mx = fmaxf(mx, tmp[i]);
            mx = fmaxf(mx, __shfl_xor_sync(0xffffffffu, mx, 1));
            mx = fmaxf(mx, __shfl_xor_sync(0xffffffffu, mx, 2));
            float se = 0.f;
#pragma unroll
            for (int i = 0; i < 16; i++) se += __expf(tmp[i] - mx);
            se += __shfl_xor_sync(0xffffffffu, se, 1);
            se += __shfl_xor_sync(0xffffffffu, se, 2);
            if (t == 0) {
                int tile = blockIdx.x * 2 + nw;   // 32 tiles of 64 cols
                part[((size_t)bh * S_LEN + m) * 32 + tile] =
                    make_float2(mx, se);
            }
        }
}

// ---------------------------------------------------------------------------
// Fused softmax + PV, 32 q-rows per CTA (grid 1024 — finer wave balance,
// 8 accum regs/thread so 4 CTAs/SM becomes RF-feasible).
// 3-stage cp.async ring; p_out via streaming stores (round-12 pipeline).
// Warps: 2m x 4n (each warp 16 rows x 16 cols of the 32x64 output).
// ---------------------------------------------------------------------------
__global__ void __launch_bounds__(256) softmax_pv(
    const __half* __restrict__ s_h, const float2* __restrict__ part,
    const __half* __restrict__ vt, float* __restrict__ p_out,
    __half* __restrict__ gaoh) {
    __shared__ __half smA[3][32 * 64];   // 4 KB per stage
    __shared__ __half smB[3][64 * 64];   // 8 KB per stage
    __shared__ float rowM[32];
    __shared__ float rowInv[32];

    const int tid = threadIdx.x;
    const int w = tid >> 5, lane = tid & 31;
    const int bh = blockIdx.y;
    const int m0 = blockIdx.x * 32;

    // ---------------- phase 0: global (M, 1/S) per row ----------------
    {
        const float2* pbase = part + ((size_t)bh * S_LEN + m0) * 32;
#pragma unroll
        for (int rr = 0; rr < 4; rr++) {
            int r = w * 4 + rr;
            float2 pm = pbase[(size_t)r * 32 + lane];   // lane = tile 0..31
            float M = pm.x;
#pragma unroll
            for (int o = 16; o; o >>= 1)
                M = fmaxf(M, __shfl_xor_sync(0xffffffffu, M, o));
            float contrib = pm.y * __expf(pm.x - M);
#pragma unroll
            for (int o = 16; o; o >>= 1)
                contrib += __shfl_xor_sync(0xffffffffu, contrib, o);
            if (lane == 0) {
                rowM[r] = M;
                rowInv[r] = 1.0f / contrib;
            }
        }
    }
    __syncthreads();

    // ---------------- phase 2: normalize + p_out + PV ----------------
    const int g = lane >> 2, t = lane & 3;
    const int mw = w >> 2, nw = w & 3;     // 2m x 4n

    const __half* Ap = s_h + ((size_t)bh * S_LEN + m0) * S_LEN;
    float* Pp = p_out + ((size_t)bh * S_LEN + m0) * S_LEN;
    const __half* Bp = vt + (size_t)bh * DK * S_LEN;
    const uint32_t sA = smem_to_u32(smA);
    const uint32_t sB = smem_to_u32(smB);

    float d[2][4];
#pragma unroll
    for (int j = 0; j < 2; j++)
#pragma unroll
        for (int r = 0; r < 4; r++) d[j][r] = 0.f;

    const int NC = S_LEN / 64;   // 32

    auto issue = [&](int kc, int stg) {
        int k0 = kc << 6;
        {
            int r = tid >> 3, c = tid & 7;   // 32 rows x 8 chunks = 256
            uint32_t dst = sA + ((stg * 2048 + r * 64 + ((c ^ (r & 7)) << 3)) << 1);
            CP_ASYNC16(dst, Ap + (size_t)r * S_LEN + k0 + (c << 3));
        }
#pragma unroll
        for (int i = 0; i < 2; i++) {
            int id = tid + (i << 8);         // 64 rows x 8 chunks = 512
            int r = id >> 3, c = id & 7;
            uint32_t dst = sB + ((stg * 4096 + r * 64 + ((c ^ (r & 7)) << 3)) << 1);
            CP_ASYNC16(dst, Bp + (size_t)r * S_LEN + k0 + (c << 3));
        }
        CP_COMMIT();
    };

    issue(0, 0);
    if (NC > 1) issue(1, 1);
    for (int kc = 0; kc < NC; kc++) {
        int k0 = kc << 6;
        if (kc + 2 < NC) {
            issue(kc + 2, (kc + 2) % 3);
            CP_WAIT2();
        } else if (kc + 1 < NC) {
            CP_WAIT1();
        } else {
            CP_WAIT0();
        }
        __syncthreads();
        int buf = kc % 3;
        __half* Ab = smA[buf];
        const __half* Bb = smB[buf];

        // normalize chunk in place + write fp32 p_attn (streaming)
        {
            int r = tid >> 3, c = tid & 7;   // one uint4 per thread
            __half* sp = Ab + r * 64 + ((c ^ (r & 7)) << 3);
            uint4 raw = *(const uint4*)sp;
            const __half2* h2 = (const __half2*)&raw;
            float M = rowM[r], inv = rowInv[r];
            float p[8];
#pragma unroll
            for (int j = 0; j < 4; j++) {
                float2 f = __half22float2(h2[j]);
                p[2 * j] = __expf(f.x - M) * inv;
                p[2 * j + 1] = __expf(f.y - M) * inv;
            }
            float* pd = Pp + (size_t)r * S_LEN + k0 + (c << 3);
            stcs4(pd, make_float4(p[0], p[1], p[2], p[3]));
            stcs4(pd + 4, make_float4(p[4], p[5], p[6], p[7]));
            uint4 pk;
            __half2* pk2 = (__half2*)&pk;
#pragma unroll
            for (int j = 0; j < 4; j++)
                pk2[j] = __floats2half2_rn(p[2 * j], p[2 * j + 1]);
            *(uint4*)sp = pk;
        }
        __syncthreads();

        // PV MMA on normalized tile
#pragma unroll
        for (int ks = 0; ks < 4; ks++) {
            const int lo = ((2 * ks) ^ g) * 8 + 2 * t;
            const int hi = ((2 * ks + 1) ^ g) * 8 + 2 * t;
            uint32_t a[4];
            {
                int r0 = mw * 16 + g;
                a[0] = *(const uint32_t*)(Ab + r0 * 64 + lo);
                a[1] = *(const uint32_t*)(Ab + (r0 + 8) * 64 + lo);
                a[2] = *(const uint32_t*)(Ab + r0 * 64 + hi);
                a[3] = *(const uint32_t*)(Ab + (r0 + 8) * 64 + hi);
            }
            uint32_t b[2][2];
#pragma unroll
            for (int ntw = 0; ntw < 2; ntw++) {
                int nr = nw * 16 + ntw * 8 + g;
                b[ntw][0] = *(const uint32_t*)(Bb + nr * 64 + lo);
                b[ntw][1] = *(const uint32_t*)(Bb + nr * 64 + hi);
            }
#pragma unroll
            for (int ntw = 0; ntw < 2; ntw++)
                mma_f16(d[ntw], a, b[ntw]);
        }
        __syncthreads();
    }

    int b = bh >> 3, h = bh & 7;
#pragma unroll
    for (int ntw = 0; ntw < 2; ntw++)
#pragma unroll
        for (int half = 0; half < 2; half++) {
            int m = m0 + mw * 16 + half * 8 + g;
            int n = nw * 16 + ntw * 8 + t * 2;
            size_t dst = ((size_t)(b * S_LEN + m)) * D_MODEL + h * DK + n;
            *(__half2*)(gaoh + dst) =
                __floats2half2_rn(d[ntw][half * 2 + 0], d[ntw][half * 2 + 1]);
        }
}

// ---------------------------------------------------------------------------
// LayerNorm kernels
// ---------------------------------------------------------------------------
__device__ __forceinline__ float blockSum256(float v, float* sred) {
#pragma unroll
    for (int o = 16; o; o >>= 1) v += __shfl_xor_sync(0xffffffffu, v, o);
    __syncthreads();
    if ((threadIdx.x & 31) == 0) sred[threadIdx.x >> 5] = v;
    __syncthreads();
    float s = sred[0];
#pragma unroll
    for (int i = 1; i < 8; i++) s += sred[i];
    return s;
}

__global__ void __launch_bounds__(256) ln_double_kernel(
    const float* __restrict__ tin, const float* __restrict__ src,
    const float* __restrict__ ga, const float* __restrict__ ba,
    const float* __restrict__ g1w, const float* __restrict__ b1w,
    float* __restrict__ hout, __half* __restrict__ hh) {
    __shared__ float sred[8];
    int m = blockIdx.x, t = threadIdx.x;
    float2 v = ((const float2*)(tin + (size_t)m * D_MODEL))[t];
    float2 xv = ((const float2*)(src + (size_t)perm_row(m) * D_MODEL))[t];
    float mu = blockSum256(v.x + v.y, sred) * (1.f / 512.f);
    float dx = v.x - mu, dy = v.y - mu;
    float var = blockSum256(dx * dx + dy * dy, sred) * (1.f / 512.f);
    float rs = rsqrtf(var + 1e-6f);
    int d0 = t * 2;
    float u0 = xv.x + dx * rs * ga[d0] + ba[d0];
    float u1 = xv.y + dy * rs * ga[d0 + 1] + ba[d0 + 1];
    mu = blockSum256(u0 + u1, sred) * (1.f / 512.f);
    dx = u0 - mu; dy = u1 - mu;
    var = blockSum256(dx * dx + dy * dy, sred) * (1.f / 512.f);
    rs = rsqrtf(var + 1e-5f);
    float h0 = dx * rs * g1w[d0] + b1w[d0];
    float h1 = dy * rs * g1w[d0 + 1] + b1w[d0 + 1];
    ((float2*)(hout + (size_t)m * D_MODEL))[t] = make_float2(h0, h1);
    ((__half2*)(hh + (size_t)m * D_MODEL))[t] = __floats2half2_rn(h0, h1);
}

__global__ void __launch_bounds__(256) ln_final_kernel(
    const float* __restrict__ tin, const float* __restrict__ g2w,
    const float* __restrict__ b2w, float* __restrict__ out) {
    __shared__ float sred[8];
    int m = blockIdx.x, t = threadIdx.x;
    float2 v = ((const float2*)(tin + (size_t)m * D_MODEL))[t];
    float mu = blockSum256(v.x + v.y, sred) * (1.f / 512.f);
    float dx = v.x - mu, dy = v.y - mu;
    float var = blockSum256(dx * dx + dy * dy, sred) * (1.f / 512.f);
    float rs = rsqrtf(var + 1e-5f);
    int d0 = t * 2;
    int b = m >> 11;
    int s = m & (S_LEN - 1);
    float2 ov = make_float2(dx * rs * g2w[d0] + b2w[d0],
                            dy * rs * g2w[d0 + 1] + b2w[d0 + 1]);
    ((float2*)(out + ((size_t)(s * B_SZ + b)) * D_MODEL))[t] = ov;
}

// ---------------------------------------------------------------------------
// Launch
// ---------------------------------------------------------------------------
#define HSMEM_BN128 (STAGES * (128 + 128) * 64 * 2)   // 98304
#define HSMEM_BN64  (STAGES * (128 + 64) * 64 * 2)    // 73728

extern "C" void kernel_launch(void* const* d_in, const int* in_sizes, int n_in,
                              void* d_out, int out_size) {
    const float* src    = (const float*)d_in[0];
    const float* sph    = (const float*)d_in[1];
    const float* w_qs   = (const float*)d_in[2];
    const float* w_ks   = (const float*)d_in[3];
    const float* w_vs   = (const float*)d_in[4];
    const float* w_fc   = (const float*)d_in[5];
    const float* g_attn = (const float*)d_in[6];
    const float* b_attn = (const float*)d_in[7];
    const float* w1     = (const float*)d_in[8];
    const float* b1     = (const float*)d_in[9];
    const float* w2     = (const float*)d_in[10];
    const float* b2     = (const float*)d_in[11];
    const float* g1w    = (const float*)d_in[12];
    const float* bn1    = (const float*)d_in[13];
    const float* g2w    = (const float*)d_in[14];
    const float* bn2    = (const float*)d_in[15];

    float* out = (float*)d_out;
    float* p_out = out + OUT_ELEMS;

    void* sp = nullptr;
    cudaGetSymbolAddress(&sp, g_scratch);
    float* scr = (float*)sp;
    float* gt1 = scr + OFF_T1;
    float* gh  = scr + OFF_H;
    __half* xh   = (__half*)(scr + OFF_XH);
    __half* qh   = (__half*)(scr + OFF_QH);
    __half* kh   = (__half*)(scr + OFF_KH);
    __half* vt_h = (__half*)(scr + OFF_VTH);
    __half* gaoh = (__half*)(scr + OFF_GAOH);
    __half* hh   = (__half*)(scr + OFF_HH);
    __half* ffh  = (__half*)(scr + OFF_FFH);
    __half* wqh  = (__half*)(scr + OFF_WQH);
    __half* wkh  = (__half*)(scr + OFF_WKH);
    __half* wvh  = (__half*)(scr + OFF_WVH);
    __half* wfch = (__half*)(scr + OFF_WFCH);
    __half* w1h  = (__half*)(scr + OFF_W1H);
    __half* w2h  = (__half*)(scr + OFF_W2H);
    __half* s_h  = (__half*)(scr + OFF_SH);
    float2* part = (float2*)(scr + OFF_PART);

    cudaFuncSetAttribute(gemm_h<0, 128>,
                         cudaFuncAttributeMaxDynamicSharedMemorySize, HSMEM_BN128);
    cudaFuncSetAttribute(gemm_h<4, 64>,
                         cudaFuncAttributeMaxDynamicSharedMemorySize, HSMEM_BN64);
    cudaFuncSetAttribute(gemm_h<5, 128>,
                         cudaFuncAttributeMaxDynamicSharedMemorySize, HSMEM_BN128);
    cudaFuncSetAttribute(gemm_h<6, 64>,
                         cudaFuncAttributeMaxDynamicSharedMemorySize, HSMEM_BN64);

    // 0. fp16 conversions (src perm + all weights)
    convert_all<<<5120, 256>>>(src, w_qs, w_ks, w_vs, w_fc, w1, w2,
                               xh, wqh, wkh, wvh, wfch, w1h, w2h);

    // 1. fused QKV (fp16): z=0 Q, z=1 K, z=2 V^T
    dim3 gqkv(D_MODEL / 128, M_ROWS / 128, 3);
    gemm_h<0, 128><<<gqkv, 256, HSMEM_BN128>>>(
        xh, D_MODEL, wqh, wkh, wvh, D_MODEL, D_MODEL,
        nullptr, nullptr, nullptr, 0, qh);

    // 2. scores = (Q K^T) * 0.125 * sph -> fp16 + softmax partials
    dim3 gsc(S_LEN / 128, S_LEN / 128, B_SZ * H_HEADS);
    scores_f16<<<gsc, 256>>>(qh, kh, sph, s_h, part);

    // 3. fused softmax + PV (32 rows/CTA, grid 1024) -> p_out + gaoh
    softmax_pv<<<dim3(S_LEN / 32, B_SZ * H_HEADS), 256>>>(s_h, part, vt_h,
                                                          p_out, gaoh);

    // 4. fc projection + residual(src perm) -> gt1 fp32
    dim3 gfc(D_MODEL / 64, M_ROWS / 128, 1);
    gemm_h<4, 64><<<gfc, 256, HSMEM_BN64>>>(
        gaoh, D_MODEL, wfch, nullptr, nullptr, D_MODEL, D_MODEL,
        gt1, nullptr, src, D_MODEL, nullptr);

    // 5. double LayerNorm -> h fp32 + hh fp16
    ln_double_kernel<<<M_ROWS, 256>>>(gt1, src, g_attn, b_attn, g1w, bn1,
                                      gh, hh);

    // 6. FFN up: relu(h @ w1^T + b1) -> ffh fp16
    dim3 gffn(F_FFN / 128, M_ROWS / 128, 1);
    gemm_h<5, 128><<<gffn, 256, HSMEM_BN128>>>(
        hh, D_MODEL, w1h, nullptr, nullptr, D_MODEL, D_MODEL,
        nullptr, b1, nullptr, F_FFN, ffh);

    // 7. FFN down + b2 + residual(h) -> gt1 fp32
    gemm_h<6, 64><<<gfc, 256, HSMEM_BN64>>>(
        ffh, F_FFN, w2h, nullptr, nullptr, F_FFN, F_FFN,
        gt1, b2, gh, D_MODEL, nullptr);

    // 8. final LN + transposed store
    ln_final_kernel<<<M_ROWS, 256>>>(gt1, g2w, bn2, out);
}